// round 2
// baseline (speedup 1.0000x reference)
#include <cuda_runtime.h>
#include <math.h>

#define BATCH 4096
#define DIM   1024
#define TEMB  256
#define NLAYERS 4

// ---------------- scratch (device globals: no allocations allowed) ----------
__device__ float g_h  [BATCH * DIM];        // residual stream
__device__ float g_xn [BATCH * DIM];        // normed/modulated activations
__device__ float g_ada[BATCH * 4 * DIM];    // adaLN params for current layer
__device__ float g_big[BATCH * 4 * DIM];    // v output / mlp hidden
__device__ float g_st [BATCH * TEMB];       // silu(t_emb)

// ---------------- epilogue modes --------------------------------------------
#define M_BIAS  0   // C = acc + bias
#define M_ADD   1   // C = acc + bias + extra
#define M_RESID 2   // C = C + acc + bias        (residual accumulate)
#define M_GELU  3   // C = gelu(acc + bias)      (exact erf)

// ---------------- tiled fp32 GEMM: C[M,N] = A[M,K] * W[N,K]^T ---------------
// Both operands K-contiguous (row-major "NT"): fully coalesced global loads.
// 128x128 tile, BK=16, 256 threads, 8x8 accum per thread.
template<int MODE>
__global__ __launch_bounds__(256) void gemm_nt(
    const float* __restrict__ A, const float* __restrict__ W,
    const float* __restrict__ bias, const float* __restrict__ extra,
    float* __restrict__ C, int M, int N, int K)
{
    __shared__ float As[16][132];
    __shared__ float Ws[16][132];

    const int bm  = blockIdx.y * 128;
    const int bn  = blockIdx.x * 128;
    const int tid = threadIdx.x;
    const int tx  = tid & 15;        // 0..15 -> 8 cols each
    const int ty  = tid >> 4;        // 0..15 -> 8 rows each
    const int lr  = tid >> 2;        // 0..63  load row
    const int lc  = (tid & 3) << 2;  // 0,4,8,12 load col (float4)

    float acc[8][8];
    #pragma unroll
    for (int i = 0; i < 8; i++)
        #pragma unroll
        for (int j = 0; j < 8; j++) acc[i][j] = 0.f;

    const float* Ap0 = A + (size_t)(bm + lr)      * K + lc;
    const float* Ap1 = A + (size_t)(bm + lr + 64) * K + lc;
    const float* Wp0 = W + (size_t)(bn + lr)      * K + lc;
    const float* Wp1 = W + (size_t)(bn + lr + 64) * K + lc;

    for (int k0 = 0; k0 < K; k0 += 16) {
        float4 a0 = *(const float4*)(Ap0 + k0);
        float4 a1 = *(const float4*)(Ap1 + k0);
        float4 w0 = *(const float4*)(Wp0 + k0);
        float4 w1 = *(const float4*)(Wp1 + k0);

        __syncthreads();   // previous iteration's reads done
        As[lc+0][lr]    = a0.x; As[lc+1][lr]    = a0.y; As[lc+2][lr]    = a0.z; As[lc+3][lr]    = a0.w;
        As[lc+0][lr+64] = a1.x; As[lc+1][lr+64] = a1.y; As[lc+2][lr+64] = a1.z; As[lc+3][lr+64] = a1.w;
        Ws[lc+0][lr]    = w0.x; Ws[lc+1][lr]    = w0.y; Ws[lc+2][lr]    = w0.z; Ws[lc+3][lr]    = w0.w;
        Ws[lc+0][lr+64] = w1.x; Ws[lc+1][lr+64] = w1.y; Ws[lc+2][lr+64] = w1.z; Ws[lc+3][lr+64] = w1.w;
        __syncthreads();

        #pragma unroll
        for (int kk = 0; kk < 16; kk++) {
            float4 av0 = *(const float4*)&As[kk][ty * 8];
            float4 av1 = *(const float4*)&As[kk][ty * 8 + 4];
            float4 bv0 = *(const float4*)&Ws[kk][tx * 8];
            float4 bv1 = *(const float4*)&Ws[kk][tx * 8 + 4];
            float a[8] = {av0.x, av0.y, av0.z, av0.w, av1.x, av1.y, av1.z, av1.w};
            float b[8] = {bv0.x, bv0.y, bv0.z, bv0.w, bv1.x, bv1.y, bv1.z, bv1.w};
            #pragma unroll
            for (int i = 0; i < 8; i++)
                #pragma unroll
                for (int j = 0; j < 8; j++)
                    acc[i][j] = fmaf(a[i], b[j], acc[i][j]);
        }
    }

    #pragma unroll
    for (int i = 0; i < 8; i++) {
        const int m = bm + ty * 8 + i;
        const size_t rowoff = (size_t)m * N;
        #pragma unroll
        for (int j = 0; j < 8; j++) {
            const int n = bn + tx * 8 + j;
            float v = acc[i][j] + bias[n];
            if (MODE == M_ADD)   v += extra[rowoff + n];
            if (MODE == M_RESID) v += C[rowoff + n];
            if (MODE == M_GELU)  v  = 0.5f * v * (1.f + erff(v * 0.70710678118654752f));
            C[rowoff + n] = v;
        }
    }
}

// ---------------- layernorm (+ optional adaLN modulation) -------------------
// one row per block, 256 threads x float4
__global__ __launch_bounds__(256) void ln_mod_k(
    const float* __restrict__ h, const float* __restrict__ g,
    const float* __restrict__ b, const float* __restrict__ ada,
    int so, int sho, float* __restrict__ out)
{
    const int row = blockIdx.x, t = threadIdx.x;
    float4 v = ((const float4*)(h + (size_t)row * DIM))[t];
    float s = v.x + v.y + v.z + v.w;
    float q = v.x*v.x + v.y*v.y + v.z*v.z + v.w*v.w;
    #pragma unroll
    for (int o = 16; o; o >>= 1) {
        s += __shfl_xor_sync(0xffffffffu, s, o);
        q += __shfl_xor_sync(0xffffffffu, q, o);
    }
    __shared__ float ss[8], qs[8];
    if ((t & 31) == 0) { ss[t >> 5] = s; qs[t >> 5] = q; }
    __syncthreads();
    s = 0.f; q = 0.f;
    #pragma unroll
    for (int i = 0; i < 8; i++) { s += ss[i]; q += qs[i]; }
    const float m   = s * (1.f / DIM);
    const float var = q * (1.f / DIM) - m * m;
    const float inv = rsqrtf(var + 1e-5f);

    const int c = t * 4;
    float4 o4;
    o4.x = (v.x - m) * inv * g[c+0] + b[c+0];
    o4.y = (v.y - m) * inv * g[c+1] + b[c+1];
    o4.z = (v.z - m) * inv * g[c+2] + b[c+2];
    o4.w = (v.w - m) * inv * g[c+3] + b[c+3];
    if (ada) {
        const float* ar = ada + (size_t)row * (4 * DIM);
        o4.x = o4.x * (1.f + ar[so + c+0]) + ar[sho + c+0];
        o4.y = o4.y * (1.f + ar[so + c+1]) + ar[sho + c+1];
        o4.z = o4.z * (1.f + ar[so + c+2]) + ar[sho + c+2];
        o4.w = o4.w * (1.f + ar[so + c+3]) + ar[sho + c+3];
    }
    ((float4*)(out + (size_t)row * DIM))[t] = o4;
}

// ---------------- silu ------------------------------------------------------
__global__ void silu_k(const float* __restrict__ in, float* __restrict__ out, int n)
{
    int i = blockIdx.x * blockDim.x + threadIdx.x;
    if (i < n) {
        float t = in[i];
        out[i] = t / (1.f + expf(-t));
    }
}

// ---------------- launch ----------------------------------------------------
extern "C" void kernel_launch(void* const* d_in, const int* in_sizes, int n_in,
                              void* d_out, int out_size)
{
    const float* x         = (const float*)d_in[0];
    const float* t_emb     = (const float*)d_in[1];
    const float* condition = (const float*)d_in[2];
    const float* in_w      = (const float*)d_in[3];
    const float* in_b      = (const float*)d_in[4];
    const float* ln1_g     = (const float*)d_in[5];
    const float* ln1_b     = (const float*)d_in[6];
    const float* wqkv      = (const float*)d_in[7];
    const float* bqkv      = (const float*)d_in[8];
    const float* wo        = (const float*)d_in[9];
    const float* bo        = (const float*)d_in[10];
    const float* ln2_g     = (const float*)d_in[11];
    const float* ln2_b     = (const float*)d_in[12];
    const float* w1        = (const float*)d_in[13];
    const float* b1        = (const float*)d_in[14];
    const float* w2        = (const float*)d_in[15];
    const float* b2        = (const float*)d_in[16];
    const float* ada_w     = (const float*)d_in[17];
    const float* ada_b     = (const float*)d_in[18];
    const float* out_ln_g  = (const float*)d_in[19];
    const float* out_ln_b  = (const float*)d_in[20];
    const float* out_w     = (const float*)d_in[21];
    const float* out_b     = (const float*)d_in[22];

    float *h, *xn, *ada, *big, *st;
    cudaGetSymbolAddress((void**)&h,   g_h);
    cudaGetSymbolAddress((void**)&xn,  g_xn);
    cudaGetSymbolAddress((void**)&ada, g_ada);
    cudaGetSymbolAddress((void**)&big, g_big);
    cudaGetSymbolAddress((void**)&st,  g_st);

    const dim3 blk(256);
    const dim3 grid_D (DIM / 128,     BATCH / 128);   // N=1024
    const dim3 grid_4D(4 * DIM / 128, BATCH / 128);   // N=4096

    // st = silu(t_emb)
    silu_k<<<(BATCH * TEMB + 255) / 256, 256>>>(t_emb, st, BATCH * TEMB);

    // h = x @ in_w^T + in_b + condition
    gemm_nt<M_ADD><<<grid_D, blk>>>(x, in_w, in_b, condition, h, BATCH, DIM, DIM);

    for (int l = 0; l < NLAYERS; l++) {
        const float* wqkv_l = wqkv  + (size_t)l * 3 * DIM * DIM;
        const float* bqkv_l = bqkv  + (size_t)l * 3 * DIM;
        const float* wo_l   = wo    + (size_t)l * DIM * DIM;
        const float* bo_l   = bo    + (size_t)l * DIM;
        const float* w1_l   = w1    + (size_t)l * 4 * DIM * DIM;
        const float* b1_l   = b1    + (size_t)l * 4 * DIM;
        const float* w2_l   = w2    + (size_t)l * DIM * 4 * DIM;
        const float* b2_l   = b2    + (size_t)l * DIM;
        const float* aw_l   = ada_w + (size_t)l * 4 * DIM * TEMB;
        const float* ab_l   = ada_b + (size_t)l * 4 * DIM;

        // ada = st @ ada_w^T + ada_b       [B, 4D], K=256
        gemm_nt<M_BIAS><<<grid_4D, blk>>>(st, aw_l, ab_l, nullptr, ada, BATCH, 4 * DIM, TEMB);

        // xn = ln(h)*(1+s1)+sh1
        ln_mod_k<<<BATCH, blk>>>(h, ln1_g + (size_t)l * DIM, ln1_b + (size_t)l * DIM,
                                 ada, 0, DIM, xn);

        // attention with seq_len==1: softmax==1 exactly => output = v.
        // v = xn @ wqkv[2D:3D]^T + bqkv[2D:3D]   (q,k never needed)
        gemm_nt<M_BIAS><<<grid_D, blk>>>(xn, wqkv_l + (size_t)2 * DIM * DIM,
                                         bqkv_l + 2 * DIM, nullptr, big, BATCH, DIM, DIM);

        // h += v @ wo^T + bo
        gemm_nt<M_RESID><<<grid_D, blk>>>(big, wo_l, bo_l, nullptr, h, BATCH, DIM, DIM);

        // xn = ln(h)*(1+s2)+sh2
        ln_mod_k<<<BATCH, blk>>>(h, ln2_g + (size_t)l * DIM, ln2_b + (size_t)l * DIM,
                                 ada, 2 * DIM, 3 * DIM, xn);

        // big = gelu(xn @ w1^T + b1)       [B, 4D]
        gemm_nt<M_GELU><<<grid_4D, blk>>>(xn, w1_l, b1_l, nullptr, big, BATCH, 4 * DIM, DIM);

        // h += big @ w2^T + b2             K=4096
        gemm_nt<M_RESID><<<grid_D, blk>>>(big, w2_l, b2_l, nullptr, h, BATCH, DIM, 4 * DIM);
    }

    // out = ln(h) @ out_w^T + out_b
    ln_mod_k<<<BATCH, blk>>>(h, out_ln_g, out_ln_b, nullptr, 0, 0, xn);
    gemm_nt<M_BIAS><<<grid_D, blk>>>(xn, out_w, out_b, nullptr, (float*)d_out, BATCH, DIM, DIM);
}

// round 4
// speedup vs baseline: 2.7095x; 2.7095x over previous
#include <cuda_runtime.h>
#include <cuda_bf16.h>
#include <math.h>
#include <stdint.h>

#define BATCH 4096
#define DIM   1024
#define TEMB  256
#define NL    4

#define EP_BIAS   0
#define EP_ADD    1
#define EP_RESID  2
#define EP_SPLIT  3
#define EP_GELUSP 4

__device__ float g_h  [BATCH * DIM];
__device__ float g_ada[BATCH * 4 * DIM];
__device__ __nv_bfloat16 g_xnh[BATCH * DIM],     g_xnl[BATCH * DIM];
__device__ __nv_bfloat16 g_sth[BATCH * TEMB],    g_stl[BATCH * TEMB];
__device__ __nv_bfloat16 g_vh [BATCH * DIM],     g_vl [BATCH * DIM];
__device__ __nv_bfloat16 g_bh [BATCH * 4 * DIM], g_bl [BATCH * 4 * DIM];
#define WTOT 48234496ull
__device__ __nv_bfloat16 g_wh[WTOT], g_wl[WTOT];

__device__ __forceinline__ uint32_t smem_u32(const void* p) {
    uint32_t a;
    asm("{ .reg .u64 t; cvta.to.shared.u64 t, %1; cvt.u32.u64 %0, t; }" : "=r"(a) : "l"(p));
    return a;
}
__device__ __forceinline__ void ldsm4(uint32_t* r, uint32_t a) {
    asm volatile("ldmatrix.sync.aligned.m8n8.x4.shared.b16 {%0,%1,%2,%3}, [%4];"
                 : "=r"(r[0]), "=r"(r[1]), "=r"(r[2]), "=r"(r[3]) : "r"(a));
}
__device__ __forceinline__ void ldsm2(uint32_t* r, uint32_t a) {
    asm volatile("ldmatrix.sync.aligned.m8n8.x2.shared.b16 {%0,%1}, [%2];"
                 : "=r"(r[0]), "=r"(r[1]) : "r"(a));
}
__device__ __forceinline__ void mma16816(float* c, const uint32_t* a, const uint32_t* b) {
    asm volatile("mma.sync.aligned.m16n8k16.row.col.f32.bf16.bf16.f32 "
                 "{%0,%1,%2,%3}, {%4,%5,%6,%7}, {%8,%9}, {%0,%1,%2,%3};"
                 : "+f"(c[0]), "+f"(c[1]), "+f"(c[2]), "+f"(c[3])
                 : "r"(a[0]), "r"(a[1]), "r"(a[2]), "r"(a[3]), "r"(b[0]), "r"(b[1]));
}

__device__ __forceinline__ void split1(float a, __nv_bfloat16& h, __nv_bfloat16& l) {
    h = __float2bfloat16(a);
    l = __float2bfloat16(a - __bfloat162float(h));
}
__device__ __forceinline__ uint32_t pack2(__nv_bfloat16 a, __nv_bfloat16 b) {
    return (uint32_t)__bfloat16_as_ushort(a) | ((uint32_t)__bfloat16_as_ushort(b) << 16);
}
__device__ __forceinline__ float gelu1(float v) {
    return 0.5f * v * (1.f + erff(v * 0.70710678118654752f));
}

// ---- GEMM: C[M,N] = A[M,K] @ W[N,K]^T, split-bf16, mma.sync (HMMA) ----
// CTA 128x128, BK=64, 8 warps (2m x 4n), warp tile 64x32, 3-stage cp.async.
#define BM 128
#define BN 128
#define STG   65536
#define OAH   0
#define OAL   16384
#define OWH   32768
#define OWL   49152
#define NSTAGE 3
#define SMEMSZ (NSTAGE * STG)

// one 128-row x 64-col bf16 tile (128B rows), SW128-style XOR swizzle
__device__ __forceinline__ void ld_tile(uint32_t tb, const __nv_bfloat16* __restrict__ g,
                                        int row0, int K, int k0, int tid) {
    const char* base = (const char*)(g + (size_t)row0 * K + k0);
    const size_t rs = (size_t)K * 2;
    #pragma unroll
    for (int i = tid; i < 128 * 8; i += 256) {
        int r = i >> 3, c2 = i & 7;
        uint32_t off = (uint32_t)(r * 128 + c2 * 16);
        uint32_t dst = tb + (off ^ ((off >> 3) & 0x70));
        asm volatile("cp.async.cg.shared.global [%0], [%1], 16;"
                     :: "r"(dst), "l"(base + (size_t)r * rs + c2 * 16));
    }
}
__device__ __forceinline__ void load_stage(uint32_t sb, int s,
    const __nv_bfloat16* Ah, const __nv_bfloat16* Al,
    const __nv_bfloat16* Wh, const __nv_bfloat16* Wl,
    int bm, int bn, int K, int c, int tid) {
    uint32_t st = sb + (uint32_t)s * STG;
    ld_tile(st + OAH, Ah, bm, K, c * 64, tid);
    ld_tile(st + OAL, Al, bm, K, c * 64, tid);
    ld_tile(st + OWH, Wh, bn, K, c * 64, tid);
    ld_tile(st + OWL, Wl, bn, K, c * 64, tid);
    asm volatile("cp.async.commit_group;" ::: "memory");
}

template<int EP>
__global__ void __launch_bounds__(256, 1)
gemm_tc(const __nv_bfloat16* __restrict__ Ah, const __nv_bfloat16* __restrict__ Al,
        const __nv_bfloat16* __restrict__ Wh, const __nv_bfloat16* __restrict__ Wl,
        const float* __restrict__ bias, const float* __restrict__ extra,
        float* __restrict__ Cf, __nv_bfloat16* __restrict__ Oh, __nv_bfloat16* __restrict__ Ol,
        int N, int K)
{
    extern __shared__ __align__(1024) char smem[];
    uint32_t sb = smem_u32(smem);
    const int tid = threadIdx.x, lane = tid & 31, wid = tid >> 5;
    const int bm = blockIdx.y * BM, bn = blockIdx.x * BN;
    const int wm = (wid & 1) * 64, wn = (wid >> 1) * 32;

    float acc[4][4][4] = {};

    // ldmatrix per-lane geometry
    const int arow = (lane & 7) + ((lane >> 3) & 1) * 8;   // x4: m within 16
    const int ac   = (lane >> 4) & 1;                      // x4: k-half
    const uint32_t axor = (uint32_t)((arow & 7) << 4);
    const int brow = lane & 7;                             // x2: n within 8
    const int bc   = (lane >> 3) & 1;                      // x2: k-half
    const uint32_t bxor = (uint32_t)((brow & 7) << 4);
    uint32_t aterm[4], bterm[4];
    #pragma unroll
    for (int mt = 0; mt < 4; mt++) aterm[mt] = (uint32_t)((wm + mt * 16 + arow) * 128);
    #pragma unroll
    for (int nt = 0; nt < 4; nt++) bterm[nt] = (uint32_t)((wn + nt * 8 + brow) * 128);

    const int nch = K >> 6;
    load_stage(sb, 0, Ah, Al, Wh, Wl, bm, bn, K, 0, tid);
    load_stage(sb, 1, Ah, Al, Wh, Wl, bm, bn, K, 1, tid);

    for (int c = 0; c < nch; c++) {
        asm volatile("cp.async.wait_group 1;" ::: "memory");
        __syncthreads();
        if (c + 2 < nch) load_stage(sb, (c + 2) % NSTAGE, Ah, Al, Wh, Wl, bm, bn, K, c + 2, tid);
        else             asm volatile("cp.async.commit_group;" ::: "memory");

        uint32_t st = sb + (uint32_t)(c % NSTAGE) * STG;
        #pragma unroll
        for (int ks = 0; ks < 4; ks++) {
            const uint32_t ka = (uint32_t)(ks * 32 + ac * 16);
            const uint32_t kb = (uint32_t)(ks * 32 + bc * 16);
            uint32_t fah[4][4], fal[4][4], fbh[4][2], fbl[4][2];
            #pragma unroll
            for (int mt = 0; mt < 4; mt++) {
                ldsm4(fah[mt], st + OAH + aterm[mt] + (ka ^ axor));
                ldsm4(fal[mt], st + OAL + aterm[mt] + (ka ^ axor));
            }
            #pragma unroll
            for (int nt = 0; nt < 4; nt++) {
                ldsm2(fbh[nt], st + OWH + bterm[nt] + (kb ^ bxor));
                ldsm2(fbl[nt], st + OWL + bterm[nt] + (kb ^ bxor));
            }
            #pragma unroll
            for (int mt = 0; mt < 4; mt++)
                #pragma unroll
                for (int nt = 0; nt < 4; nt++) {
                    mma16816(acc[mt][nt], fah[mt], fbh[nt]);
                    mma16816(acc[mt][nt], fal[mt], fbh[nt]);
                    mma16816(acc[mt][nt], fah[mt], fbl[nt]);
                }
        }
    }

    // ---- epilogue from registers ----
    const int r0b = bm + wm + (lane >> 2);
    const int c0b = bn + wn + 2 * (lane & 3);
    #pragma unroll
    for (int mt = 0; mt < 4; mt++) {
        const int row0 = r0b + mt * 16, row1 = row0 + 8;
        #pragma unroll
        for (int nt = 0; nt < 4; nt++) {
            const int col = c0b + nt * 8;
            const float b0 = bias[col], b1 = bias[col + 1];
            float v00 = acc[mt][nt][0] + b0, v01 = acc[mt][nt][1] + b1;
            float v10 = acc[mt][nt][2] + b0, v11 = acc[mt][nt][3] + b1;
            const size_t g0 = (size_t)row0 * N + col, g1 = (size_t)row1 * N + col;

            if (EP == EP_GELUSP) {
                v00 = gelu1(v00); v01 = gelu1(v01); v10 = gelu1(v10); v11 = gelu1(v11);
            }
            if (EP == EP_SPLIT || EP == EP_GELUSP) {
                __nv_bfloat16 h0,l0,h1,l1;
                split1(v00,h0,l0); split1(v01,h1,l1);
                *(uint32_t*)(Oh + g0) = pack2(h0,h1);
                *(uint32_t*)(Ol + g0) = pack2(l0,l1);
                split1(v10,h0,l0); split1(v11,h1,l1);
                *(uint32_t*)(Oh + g1) = pack2(h0,h1);
                *(uint32_t*)(Ol + g1) = pack2(l0,l1);
            } else if (EP == EP_RESID) {
                float2 t0 = *(float2*)(Cf + g0);
                float2 t1 = *(float2*)(Cf + g1);
                t0.x += v00; t0.y += v01; t1.x += v10; t1.y += v11;
                *(float2*)(Cf + g0) = t0;
                *(float2*)(Cf + g1) = t1;
            } else if (EP == EP_ADD) {
                float2 e0 = *(const float2*)(extra + g0);
                float2 e1 = *(const float2*)(extra + g1);
                *(float2*)(Cf + g0) = make_float2(v00 + e0.x, v01 + e0.y);
                *(float2*)(Cf + g1) = make_float2(v10 + e1.x, v11 + e1.y);
            } else {
                *(float2*)(Cf + g0) = make_float2(v00, v01);
                *(float2*)(Cf + g1) = make_float2(v10, v11);
            }
        }
    }
}

// ---- elementwise ----
template<int SILU>
__global__ void split_k(const float* __restrict__ s, __nv_bfloat16* __restrict__ oh,
                        __nv_bfloat16* __restrict__ ol, int n) {
    int i = (blockIdx.x * blockDim.x + threadIdx.x) * 4;
    if (i >= n) return;
    float4 v = *(const float4*)(s + i);
    if (SILU) {
        v.x /= (1.f + expf(-v.x)); v.y /= (1.f + expf(-v.y));
        v.z /= (1.f + expf(-v.z)); v.w /= (1.f + expf(-v.w));
    }
    __nv_bfloat16 h0,h1,h2,h3,l0,l1,l2,l3;
    split1(v.x,h0,l0); split1(v.y,h1,l1); split1(v.z,h2,l2); split1(v.w,h3,l3);
    *(uint2*)(oh + i) = make_uint2(pack2(h0,h1), pack2(h2,h3));
    *(uint2*)(ol + i) = make_uint2(pack2(l0,l1), pack2(l2,l3));
}

__global__ __launch_bounds__(256) void ln_split_k(
    const float* __restrict__ h, const float* __restrict__ g,
    const float* __restrict__ b, const float* __restrict__ ada,
    int so, int sho, __nv_bfloat16* __restrict__ oh, __nv_bfloat16* __restrict__ ol)
{
    const int row = blockIdx.x, t = threadIdx.x;
    float4 v = ((const float4*)(h + (size_t)row * DIM))[t];
    float s = v.x + v.y + v.z + v.w;
    float q = v.x*v.x + v.y*v.y + v.z*v.z + v.w*v.w;
    #pragma unroll
    for (int o = 16; o; o >>= 1) {
        s += __shfl_xor_sync(0xffffffffu, s, o);
        q += __shfl_xor_sync(0xffffffffu, q, o);
    }
    __shared__ float ss[8], qs[8];
    if ((t & 31) == 0) { ss[t >> 5] = s; qs[t >> 5] = q; }
    __syncthreads();
    s = 0.f; q = 0.f;
    #pragma unroll
    for (int i = 0; i < 8; i++) { s += ss[i]; q += qs[i]; }
    const float m = s * (1.f / DIM);
    const float inv = rsqrtf(q * (1.f / DIM) - m * m + 1e-5f);
    const int c = t * 4;
    float o0 = (v.x - m) * inv * g[c+0] + b[c+0];
    float o1 = (v.y - m) * inv * g[c+1] + b[c+1];
    float o2 = (v.z - m) * inv * g[c+2] + b[c+2];
    float o3 = (v.w - m) * inv * g[c+3] + b[c+3];
    if (ada) {
        const float* ar = ada + (size_t)row * (4 * DIM);
        o0 = o0 * (1.f + ar[so+c+0]) + ar[sho+c+0];
        o1 = o1 * (1.f + ar[so+c+1]) + ar[sho+c+1];
        o2 = o2 * (1.f + ar[so+c+2]) + ar[sho+c+2];
        o3 = o3 * (1.f + ar[so+c+3]) + ar[sho+c+3];
    }
    __nv_bfloat16 h0,h1,h2,h3,l0,l1,l2,l3;
    split1(o0,h0,l0); split1(o1,h1,l1); split1(o2,h2,l2); split1(o3,h3,l3);
    *(uint2*)(oh + (size_t)row * DIM + c) = make_uint2(pack2(h0,h1), pack2(h2,h3));
    *(uint2*)(ol + (size_t)row * DIM + c) = make_uint2(pack2(l0,l1), pack2(l2,l3));
}

// ---- launch ----
extern "C" void kernel_launch(void* const* d_in, const int* in_sizes, int n_in,
                              void* d_out, int out_size)
{
    const float* x        = (const float*)d_in[0];
    const float* t_emb    = (const float*)d_in[1];
    const float* condition= (const float*)d_in[2];
    const float* in_w     = (const float*)d_in[3];
    const float* in_b     = (const float*)d_in[4];
    const float* ln1_g    = (const float*)d_in[5];
    const float* ln1_b    = (const float*)d_in[6];
    const float* wqkv     = (const float*)d_in[7];
    const float* bqkv     = (const float*)d_in[8];
    const float* wo       = (const float*)d_in[9];
    const float* bo       = (const float*)d_in[10];
    const float* ln2_g    = (const float*)d_in[11];
    const float* ln2_b    = (const float*)d_in[12];
    const float* w1       = (const float*)d_in[13];
    const float* b1       = (const float*)d_in[14];
    const float* w2       = (const float*)d_in[15];
    const float* b2       = (const float*)d_in[16];
    const float* ada_w    = (const float*)d_in[17];
    const float* ada_b    = (const float*)d_in[18];
    const float* out_ln_g = (const float*)d_in[19];
    const float* out_ln_b = (const float*)d_in[20];
    const float* out_w    = (const float*)d_in[21];
    const float* out_b    = (const float*)d_in[22];

    float *h, *ada;
    __nv_bfloat16 *xnh,*xnl,*sth,*stl,*vh,*vl,*bh,*bl,*wh,*wl;
    cudaGetSymbolAddress((void**)&h,   g_h);
    cudaGetSymbolAddress((void**)&ada, g_ada);
    cudaGetSymbolAddress((void**)&xnh, g_xnh); cudaGetSymbolAddress((void**)&xnl, g_xnl);
    cudaGetSymbolAddress((void**)&sth, g_sth); cudaGetSymbolAddress((void**)&stl, g_stl);
    cudaGetSymbolAddress((void**)&vh,  g_vh);  cudaGetSymbolAddress((void**)&vl,  g_vl);
    cudaGetSymbolAddress((void**)&bh,  g_bh);  cudaGetSymbolAddress((void**)&bl,  g_bl);
    cudaGetSymbolAddress((void**)&wh,  g_wh);  cudaGetSymbolAddress((void**)&wl,  g_wl);

    cudaFuncSetAttribute(gemm_tc<EP_BIAS>,   cudaFuncAttributeMaxDynamicSharedMemorySize, SMEMSZ);
    cudaFuncSetAttribute(gemm_tc<EP_ADD>,    cudaFuncAttributeMaxDynamicSharedMemorySize, SMEMSZ);
    cudaFuncSetAttribute(gemm_tc<EP_RESID>,  cudaFuncAttributeMaxDynamicSharedMemorySize, SMEMSZ);
    cudaFuncSetAttribute(gemm_tc<EP_SPLIT>,  cudaFuncAttributeMaxDynamicSharedMemorySize, SMEMSZ);
    cudaFuncSetAttribute(gemm_tc<EP_GELUSP>, cudaFuncAttributeMaxDynamicSharedMemorySize, SMEMSZ);

    const size_t D2 = (size_t)DIM * DIM;
    const size_t LSTRIDE = 11 * D2;
    const size_t OFF_L0 = D2, OFF_OUT = D2 + 4 * LSTRIDE;

    const int sb = 256;
    auto spl = [&](const float* src, __nv_bfloat16* oh, __nv_bfloat16* ol, size_t n) {
        split_k<0><<<(int)(n / 4 + sb - 1) / sb, sb>>>(src, oh, ol, (int)n);
    };

    spl(x, xnh, xnl, (size_t)BATCH * DIM);
    split_k<1><<<(BATCH * TEMB / 4 + sb - 1) / sb, sb>>>(t_emb, sth, stl, BATCH * TEMB);
    spl(in_w, wh, wl, D2);
    for (int l = 0; l < NL; l++) {
        size_t o = OFF_L0 + (size_t)l * LSTRIDE;
        spl(ada_w + (size_t)l * 4 * DIM * TEMB, wh + o,          wl + o,          4 * (size_t)DIM * TEMB);
        spl(wqkv + (size_t)l * 3 * D2 + 2 * D2, wh + o + D2,     wl + o + D2,     D2);
        spl(wo + (size_t)l * D2,                wh + o + 2 * D2, wl + o + 2 * D2, D2);
        spl(w1 + (size_t)l * 4 * D2,            wh + o + 3 * D2, wl + o + 3 * D2, 4 * D2);
        spl(w2 + (size_t)l * 4 * D2,            wh + o + 7 * D2, wl + o + 7 * D2, 4 * D2);
    }
    spl(out_w, wh + OFF_OUT, wl + OFF_OUT, D2);

    const dim3 blk(256);
    const dim3 gD (DIM / BN, BATCH / BM);      // (8, 32)
    const dim3 g4D(4 * DIM / BN, BATCH / BM);  // (32, 32)

    gemm_tc<EP_ADD><<<gD, blk, SMEMSZ>>>(xnh, xnl, wh, wl, in_b, condition, h, nullptr, nullptr, DIM, DIM);

    for (int l = 0; l < NL; l++) {
        size_t o = OFF_L0 + (size_t)l * LSTRIDE;
        gemm_tc<EP_BIAS><<<g4D, blk, SMEMSZ>>>(sth, stl, wh + o, wl + o, ada_b + (size_t)l * 4 * DIM,
                                               nullptr, ada, nullptr, nullptr, 4 * DIM, TEMB);
        ln_split_k<<<BATCH, 256>>>(h, ln1_g + (size_t)l * DIM, ln1_b + (size_t)l * DIM, ada, 0, DIM, xnh, xnl);
        gemm_tc<EP_SPLIT><<<gD, blk, SMEMSZ>>>(xnh, xnl, wh + o + D2, wl + o + D2,
                                               bqkv + (size_t)l * 3 * DIM + 2 * DIM, nullptr,
                                               nullptr, vh, vl, DIM, DIM);
        gemm_tc<EP_RESID><<<gD, blk, SMEMSZ>>>(vh, vl, wh + o + 2 * D2, wl + o + 2 * D2,
                                               bo + (size_t)l * DIM, nullptr, h, nullptr, nullptr, DIM, DIM);
        ln_split_k<<<BATCH, 256>>>(h, ln2_g + (size_t)l * DIM, ln2_b + (size_t)l * DIM, ada, 2 * DIM, 3 * DIM, xnh, xnl);
        gemm_tc<EP_GELUSP><<<g4D, blk, SMEMSZ>>>(xnh, xnl, wh + o + 3 * D2, wl + o + 3 * D2,
                                                 b1 + (size_t)l * 4 * DIM, nullptr,
                                                 nullptr, bh, bl, 4 * DIM, DIM);
        gemm_tc<EP_RESID><<<gD, blk, SMEMSZ>>>(bh, bl, wh + o + 7 * D2, wl + o + 7 * D2,
                                               b2 + (size_t)l * DIM, nullptr, h, nullptr, nullptr, DIM, 4 * DIM);
    }

    ln_split_k<<<BATCH, 256>>>(h, out_ln_g, out_ln_b, nullptr, 0, 0, xnh, xnl);
    gemm_tc<EP_BIAS><<<gD, blk, SMEMSZ>>>(xnh, xnl, wh + OFF_OUT, wl + OFF_OUT, out_b, nullptr,
                                          (float*)d_out, nullptr, nullptr, DIM, DIM);
}

// round 5
// speedup vs baseline: 3.5196x; 1.2990x over previous
#include <cuda_runtime.h>
#include <cuda_fp16.h>
#include <math.h>
#include <stdint.h>

#define BATCH 4096
#define DIM   1024
#define TEMB  256
#define NL    4

#define EP_BIAS   0
#define EP_ADD    1
#define EP_RESID  2
#define EP_SPLIT  3
#define EP_GELUSP 4

__device__ float g_h  [BATCH * DIM];
__device__ float g_ada[BATCH * 4 * DIM];
__device__ __half g_xnh[BATCH * DIM],     g_xnl[BATCH * DIM];
__device__ __half g_sth[BATCH * TEMB],    g_stl[BATCH * TEMB];
__device__ __half g_vh [BATCH * DIM],     g_vl [BATCH * DIM];
__device__ __half g_bh [BATCH * 4 * DIM], g_bl [BATCH * 4 * DIM];
#define WTOT 48234496ull
__device__ __half g_w[WTOT];

__device__ __forceinline__ uint32_t smem_u32(const void* p) {
    uint32_t a;
    asm("{ .reg .u64 t; cvta.to.shared.u64 t, %1; cvt.u32.u64 %0, t; }" : "=r"(a) : "l"(p));
    return a;
}
__device__ __forceinline__ void ldsm4(uint32_t* r, uint32_t a) {
    asm volatile("ldmatrix.sync.aligned.m8n8.x4.shared.b16 {%0,%1,%2,%3}, [%4];"
                 : "=r"(r[0]), "=r"(r[1]), "=r"(r[2]), "=r"(r[3]) : "r"(a));
}
__device__ __forceinline__ void mma16816(float* c, const uint32_t* a, const uint32_t* b) {
    asm volatile("mma.sync.aligned.m16n8k16.row.col.f32.f16.f16.f32 "
                 "{%0,%1,%2,%3}, {%4,%5,%6,%7}, {%8,%9}, {%0,%1,%2,%3};"
                 : "+f"(c[0]), "+f"(c[1]), "+f"(c[2]), "+f"(c[3])
                 : "r"(a[0]), "r"(a[1]), "r"(a[2]), "r"(a[3]), "r"(b[0]), "r"(b[1]));
}
__device__ __forceinline__ void split1(float a, __half& h, __half& l) {
    h = __float2half_rn(a);
    l = __float2half_rn(a - __half2float(h));
}
__device__ __forceinline__ uint32_t pack2(__half a, __half b) {
    return (uint32_t)__half_as_ushort(a) | ((uint32_t)__half_as_ushort(b) << 16);
}
__device__ __forceinline__ float gelu1(float v) {
    return 0.5f * v * (1.f + erff(v * 0.70710678118654752f));
}

// ---- GEMM: C[M,N] = A[M,K] @ W[N,K]^T ----
// A = (ah + al) fp16 split, W = fp16.  CTA 128x256, 8 warps (2m x 4n),
// warp tile 64x64, BK=64, 3-stage cp.async, mma.sync m16n8k16 fp16.
#define BM 128
#define BN 256
#define OAH 0
#define OAL 16384
#define OW  32768
#define STG 65536
#define NSTAGE 3
#define SMEMSZ (NSTAGE * STG)

__device__ __forceinline__ void ld_tile(uint32_t tb, const __half* __restrict__ g,
                                        int row0, int K, int k0, int nrows, int tid) {
    const char* base = (const char*)(g + (size_t)row0 * K + k0);
    const size_t rs = (size_t)K * 2;
    #pragma unroll
    for (int i = tid; i < nrows * 8; i += 256) {
        int r = i >> 3, c2 = i & 7;
        uint32_t off = (uint32_t)(r * 128 + c2 * 16);
        uint32_t dst = tb + (off ^ ((off >> 3) & 0x70));
        asm volatile("cp.async.cg.shared.global [%0], [%1], 16;"
                     :: "r"(dst), "l"(base + (size_t)r * rs + c2 * 16));
    }
}
__device__ __forceinline__ void load_stage(uint32_t sb, int s,
    const __half* Ah, const __half* Al, const __half* W,
    int bm, int bn, int K, int c, int tid) {
    uint32_t st = sb + (uint32_t)s * STG;
    ld_tile(st + OAH, Ah, bm, K, c * 64, 128, tid);
    ld_tile(st + OAL, Al, bm, K, c * 64, 128, tid);
    ld_tile(st + OW,  W,  bn, K, c * 64, 256, tid);
    asm volatile("cp.async.commit_group;" ::: "memory");
}

template<int EP>
__global__ void __launch_bounds__(256, 1)
gemm_tc(const __half* __restrict__ Ah, const __half* __restrict__ Al,
        const __half* __restrict__ W,
        const float* __restrict__ bias, const float* __restrict__ extra,
        float* __restrict__ Cf, __half* __restrict__ Oh, __half* __restrict__ Ol,
        int N, int K)
{
    extern __shared__ __align__(1024) char smem[];
    uint32_t sb = smem_u32(smem);
    const int tid = threadIdx.x, lane = tid & 31, wid = tid >> 5;
    const int bm = blockIdx.y * BM, bn = blockIdx.x * BN;
    const int wm = (wid & 1) * 64, wn = (wid >> 1) * 64;

    float acc[4][8][4] = {};

    // A ldmatrix (x4 over 16 m-rows, k-halves by lane>>4)
    const int arow = (lane & 7) + ((lane >> 3) & 1) * 8;
    const int ac   = (lane >> 4) & 1;
    const uint32_t axor = (uint32_t)((arow & 7) << 4);
    uint32_t aterm[4];
    #pragma unroll
    for (int mt = 0; mt < 4; mt++) aterm[mt] = (uint32_t)((wm + mt * 16 + arow) * 128);

    // B ldmatrix (x4 covering two n8-tiles x two k-halves)
    const int brow = lane & 7;
    const int bk   = (lane >> 3) & 1;
    const int bn8  = (lane >> 4) & 1;
    const uint32_t bxor = (uint32_t)(brow << 4);
    uint32_t bterm[4];
    #pragma unroll
    for (int ntp = 0; ntp < 4; ntp++)
        bterm[ntp] = (uint32_t)((wn + ntp * 16 + bn8 * 8 + brow) * 128);

    const int nch = K >> 6;
    load_stage(sb, 0, Ah, Al, W, bm, bn, K, 0, tid);
    load_stage(sb, 1, Ah, Al, W, bm, bn, K, 1, tid);

    for (int c = 0; c < nch; c++) {
        asm volatile("cp.async.wait_group 1;" ::: "memory");
        __syncthreads();
        if (c + 2 < nch) load_stage(sb, (c + 2) % NSTAGE, Ah, Al, W, bm, bn, K, c + 2, tid);
        else             asm volatile("cp.async.commit_group;" ::: "memory");

        uint32_t st = sb + (uint32_t)(c % NSTAGE) * STG;
        #pragma unroll
        for (int ks = 0; ks < 4; ks++) {
            const uint32_t ka = (uint32_t)(ks * 32 + ac * 16);
            const uint32_t kb = (uint32_t)(ks * 32 + bk * 16);
            uint32_t fb[8][2];
            #pragma unroll
            for (int ntp = 0; ntp < 4; ntp++)
                ldsm4(&fb[2 * ntp][0], st + OW + bterm[ntp] + (kb ^ bxor));
            #pragma unroll
            for (int mt = 0; mt < 4; mt++) {
                uint32_t fh[4], fl[4];
                ldsm4(fh, st + OAH + aterm[mt] + (ka ^ axor));
                ldsm4(fl, st + OAL + aterm[mt] + (ka ^ axor));
                #pragma unroll
                for (int nt = 0; nt < 8; nt++) {
                    mma16816(acc[mt][nt], fh, fb[nt]);
                    mma16816(acc[mt][nt], fl, fb[nt]);
                }
            }
        }
    }

    // ---- epilogue ----
    const int r0b = bm + wm + (lane >> 2);
    const int c0b = bn + wn + 2 * (lane & 3);
    #pragma unroll
    for (int mt = 0; mt < 4; mt++) {
        const int row0 = r0b + mt * 16, row1 = row0 + 8;
        #pragma unroll
        for (int nt = 0; nt < 8; nt++) {
            const int col = c0b + nt * 8;
            const float b0 = bias[col], b1 = bias[col + 1];
            float v00 = acc[mt][nt][0] + b0, v01 = acc[mt][nt][1] + b1;
            float v10 = acc[mt][nt][2] + b0, v11 = acc[mt][nt][3] + b1;
            const size_t g0 = (size_t)row0 * N + col, g1 = (size_t)row1 * N + col;

            if (EP == EP_GELUSP) {
                v00 = gelu1(v00); v01 = gelu1(v01); v10 = gelu1(v10); v11 = gelu1(v11);
            }
            if (EP == EP_SPLIT || EP == EP_GELUSP) {
                __half h0,l0,h1,l1;
                split1(v00,h0,l0); split1(v01,h1,l1);
                *(uint32_t*)(Oh + g0) = pack2(h0,h1);
                *(uint32_t*)(Ol + g0) = pack2(l0,l1);
                split1(v10,h0,l0); split1(v11,h1,l1);
                *(uint32_t*)(Oh + g1) = pack2(h0,h1);
                *(uint32_t*)(Ol + g1) = pack2(l0,l1);
            } else if (EP == EP_RESID) {
                float2 t0 = *(float2*)(Cf + g0);
                float2 t1 = *(float2*)(Cf + g1);
                t0.x += v00; t0.y += v01; t1.x += v10; t1.y += v11;
                *(float2*)(Cf + g0) = t0;
                *(float2*)(Cf + g1) = t1;
            } else if (EP == EP_ADD) {
                float2 e0 = *(const float2*)(extra + g0);
                float2 e1 = *(const float2*)(extra + g1);
                *(float2*)(Cf + g0) = make_float2(v00 + e0.x, v01 + e0.y);
                *(float2*)(Cf + g1) = make_float2(v10 + e1.x, v11 + e1.y);
            } else {
                *(float2*)(Cf + g0) = make_float2(v00, v01);
                *(float2*)(Cf + g1) = make_float2(v10, v11);
            }
        }
    }
}

// ---- elementwise ----
__global__ void cvt_k(const float* __restrict__ s, __half* __restrict__ o, int n) {
    int i = (blockIdx.x * blockDim.x + threadIdx.x) * 4;
    if (i >= n) return;
    float4 v = *(const float4*)(s + i);
    *(uint2*)(o + i) = make_uint2(pack2(__float2half_rn(v.x), __float2half_rn(v.y)),
                                  pack2(__float2half_rn(v.z), __float2half_rn(v.w)));
}
template<int SILU>
__global__ void split_k(const float* __restrict__ s, __half* __restrict__ oh,
                        __half* __restrict__ ol, int n) {
    int i = (blockIdx.x * blockDim.x + threadIdx.x) * 4;
    if (i >= n) return;
    float4 v = *(const float4*)(s + i);
    if (SILU) {
        v.x /= (1.f + expf(-v.x)); v.y /= (1.f + expf(-v.y));
        v.z /= (1.f + expf(-v.z)); v.w /= (1.f + expf(-v.w));
    }
    __half h0,h1,h2,h3,l0,l1,l2,l3;
    split1(v.x,h0,l0); split1(v.y,h1,l1); split1(v.z,h2,l2); split1(v.w,h3,l3);
    *(uint2*)(oh + i) = make_uint2(pack2(h0,h1), pack2(h2,h3));
    *(uint2*)(ol + i) = make_uint2(pack2(l0,l1), pack2(l2,l3));
}

__global__ __launch_bounds__(256) void ln_split_k(
    const float* __restrict__ h, const float* __restrict__ g,
    const float* __restrict__ b, const float* __restrict__ ada,
    int so, int sho, __half* __restrict__ oh, __half* __restrict__ ol)
{
    const int row = blockIdx.x, t = threadIdx.x;
    float4 v = ((const float4*)(h + (size_t)row * DIM))[t];
    float s = v.x + v.y + v.z + v.w;
    float q = v.x*v.x + v.y*v.y + v.z*v.z + v.w*v.w;
    #pragma unroll
    for (int o = 16; o; o >>= 1) {
        s += __shfl_xor_sync(0xffffffffu, s, o);
        q += __shfl_xor_sync(0xffffffffu, q, o);
    }
    __shared__ float ss[8], qs[8];
    if ((t & 31) == 0) { ss[t >> 5] = s; qs[t >> 5] = q; }
    __syncthreads();
    s = 0.f; q = 0.f;
    #pragma unroll
    for (int i = 0; i < 8; i++) { s += ss[i]; q += qs[i]; }
    const float m = s * (1.f / DIM);
    const float inv = rsqrtf(q * (1.f / DIM) - m * m + 1e-5f);
    const int c = t * 4;
    float o0 = (v.x - m) * inv * g[c+0] + b[c+0];
    float o1 = (v.y - m) * inv * g[c+1] + b[c+1];
    float o2 = (v.z - m) * inv * g[c+2] + b[c+2];
    float o3 = (v.w - m) * inv * g[c+3] + b[c+3];
    if (ada) {
        const float* ar = ada + (size_t)row * (4 * DIM);
        o0 = o0 * (1.f + ar[so+c+0]) + ar[sho+c+0];
        o1 = o1 * (1.f + ar[so+c+1]) + ar[sho+c+1];
        o2 = o2 * (1.f + ar[so+c+2]) + ar[sho+c+2];
        o3 = o3 * (1.f + ar[so+c+3]) + ar[sho+c+3];
    }
    __half h0,h1,h2,h3,l0,l1,l2,l3;
    split1(o0,h0,l0); split1(o1,h1,l1); split1(o2,h2,l2); split1(o3,h3,l3);
    *(uint2*)(oh + (size_t)row * DIM + c) = make_uint2(pack2(h0,h1), pack2(h2,h3));
    *(uint2*)(ol + (size_t)row * DIM + c) = make_uint2(pack2(l0,l1), pack2(l2,l3));
}

// ---- launch ----
extern "C" void kernel_launch(void* const* d_in, const int* in_sizes, int n_in,
                              void* d_out, int out_size)
{
    const float* x        = (const float*)d_in[0];
    const float* t_emb    = (const float*)d_in[1];
    const float* condition= (const float*)d_in[2];
    const float* in_w     = (const float*)d_in[3];
    const float* in_b     = (const float*)d_in[4];
    const float* ln1_g    = (const float*)d_in[5];
    const float* ln1_b    = (const float*)d_in[6];
    const float* wqkv     = (const float*)d_in[7];
    const float* bqkv     = (const float*)d_in[8];
    const float* wo       = (const float*)d_in[9];
    const float* bo       = (const float*)d_in[10];
    const float* ln2_g    = (const float*)d_in[11];
    const float* ln2_b    = (const float*)d_in[12];
    const float* w1       = (const float*)d_in[13];
    const float* b1       = (const float*)d_in[14];
    const float* w2       = (const float*)d_in[15];
    const float* b2       = (const float*)d_in[16];
    const float* ada_w    = (const float*)d_in[17];
    const float* ada_b    = (const float*)d_in[18];
    const float* out_ln_g = (const float*)d_in[19];
    const float* out_ln_b = (const float*)d_in[20];
    const float* out_w    = (const float*)d_in[21];
    const float* out_b    = (const float*)d_in[22];

    float *h, *ada;
    __half *xnh,*xnl,*sth,*stl,*vh,*vl,*bh,*bl,*w;
    cudaGetSymbolAddress((void**)&h,   g_h);
    cudaGetSymbolAddress((void**)&ada, g_ada);
    cudaGetSymbolAddress((void**)&xnh, g_xnh); cudaGetSymbolAddress((void**)&xnl, g_xnl);
    cudaGetSymbolAddress((void**)&sth, g_sth); cudaGetSymbolAddress((void**)&stl, g_stl);
    cudaGetSymbolAddress((void**)&vh,  g_vh);  cudaGetSymbolAddress((void**)&vl,  g_vl);
    cudaGetSymbolAddress((void**)&bh,  g_bh);  cudaGetSymbolAddress((void**)&bl,  g_bl);
    cudaGetSymbolAddress((void**)&w,   g_w);

    cudaFuncSetAttribute(gemm_tc<EP_BIAS>,   cudaFuncAttributeMaxDynamicSharedMemorySize, SMEMSZ);
    cudaFuncSetAttribute(gemm_tc<EP_ADD>,    cudaFuncAttributeMaxDynamicSharedMemorySize, SMEMSZ);
    cudaFuncSetAttribute(gemm_tc<EP_RESID>,  cudaFuncAttributeMaxDynamicSharedMemorySize, SMEMSZ);
    cudaFuncSetAttribute(gemm_tc<EP_SPLIT>,  cudaFuncAttributeMaxDynamicSharedMemorySize, SMEMSZ);
    cudaFuncSetAttribute(gemm_tc<EP_GELUSP>, cudaFuncAttributeMaxDynamicSharedMemorySize, SMEMSZ);

    const size_t D2 = (size_t)DIM * DIM;
    const size_t LSTRIDE = 11 * D2;
    const size_t OFF_L0 = D2, OFF_OUT = D2 + 4 * LSTRIDE;

    const int sb = 256;
    auto cvt = [&](const float* src, __half* o, size_t n) {
        cvt_k<<<(int)(n / 4 + sb - 1) / sb, sb>>>(src, o, (int)n);
    };

    split_k<0><<<(BATCH * DIM / 4 + sb - 1) / sb, sb>>>(x, xnh, xnl, BATCH * DIM);
    split_k<1><<<(BATCH * TEMB / 4 + sb - 1) / sb, sb>>>(t_emb, sth, stl, BATCH * TEMB);
    cvt(in_w, w, D2);
    for (int l = 0; l < NL; l++) {
        size_t o = OFF_L0 + (size_t)l * LSTRIDE;
        cvt(ada_w + (size_t)l * 4 * DIM * TEMB, w + o,          4 * (size_t)DIM * TEMB);
        cvt(wqkv + (size_t)l * 3 * D2 + 2 * D2, w + o + D2,     D2);
        cvt(wo + (size_t)l * D2,                w + o + 2 * D2, D2);
        cvt(w1 + (size_t)l * 4 * D2,            w + o + 3 * D2, 4 * D2);
        cvt(w2 + (size_t)l * 4 * D2,            w + o + 7 * D2, 4 * D2);
    }
    cvt(out_w, w + OFF_OUT, D2);

    const dim3 blk(256);
    const dim3 gD (DIM / BN, BATCH / BM);      // (4, 32)
    const dim3 g4D(4 * DIM / BN, BATCH / BM);  // (16, 32)

    gemm_tc<EP_ADD><<<gD, blk, SMEMSZ>>>(xnh, xnl, w, in_b, condition, h, nullptr, nullptr, DIM, DIM);

    for (int l = 0; l < NL; l++) {
        size_t o = OFF_L0 + (size_t)l * LSTRIDE;
        gemm_tc<EP_BIAS><<<g4D, blk, SMEMSZ>>>(sth, stl, w + o, ada_b + (size_t)l * 4 * DIM,
                                               nullptr, ada, nullptr, nullptr, 4 * DIM, TEMB);
        ln_split_k<<<BATCH, 256>>>(h, ln1_g + (size_t)l * DIM, ln1_b + (size_t)l * DIM, ada, 0, DIM, xnh, xnl);
        gemm_tc<EP_SPLIT><<<gD, blk, SMEMSZ>>>(xnh, xnl, w + o + D2,
                                               bqkv + (size_t)l * 3 * DIM + 2 * DIM, nullptr,
                                               nullptr, vh, vl, DIM, DIM);
        gemm_tc<EP_RESID><<<gD, blk, SMEMSZ>>>(vh, vl, w + o + 2 * D2,
                                               bo + (size_t)l * DIM, nullptr, h, nullptr, nullptr, DIM, DIM);
        ln_split_k<<<BATCH, 256>>>(h, ln2_g + (size_t)l * DIM, ln2_b + (size_t)l * DIM, ada, 2 * DIM, 3 * DIM, xnh, xnl);
        gemm_tc<EP_GELUSP><<<g4D, blk, SMEMSZ>>>(xnh, xnl, w + o + 3 * D2,
                                                 b1 + (size_t)l * 4 * DIM, nullptr,
                                                 nullptr, bh, bl, 4 * DIM, DIM);
        gemm_tc<EP_RESID><<<gD, blk, SMEMSZ>>>(bh, bl, w + o + 7 * D2,
                                               b2 + (size_t)l * DIM, nullptr, h, nullptr, nullptr, DIM, 4 * DIM);
    }

    ln_split_k<<<BATCH, 256>>>(h, out_ln_g, out_ln_b, nullptr, 0, 0, xnh, xnl);
    gemm_tc<EP_BIAS><<<gD, blk, SMEMSZ>>>(xnh, xnl, w + OFF_OUT, out_b, nullptr,
                                          (float*)d_out, nullptr, nullptr, DIM, DIM);
}

// round 6
// speedup vs baseline: 3.7250x; 1.0584x over previous
#include <cuda_runtime.h>
#include <cuda_fp16.h>
#include <math.h>
#include <stdint.h>

#define BATCH 4096
#define DIM   1024
#define TEMB  256
#define NL    4

#define EP_BIAS   0
#define EP_ADD    1
#define EP_RESID  2
#define EP_SPLIT  3
#define EP_GELUSP 4

__device__ float g_h  [BATCH * DIM];
__device__ float g_ada[(size_t)BATCH * 16 * DIM];   // all 4 layers' adaLN params
__device__ __half g_xnh[BATCH * DIM],     g_xnl[BATCH * DIM];
__device__ __half g_sth[BATCH * TEMB],    g_stl[BATCH * TEMB];
__device__ __half g_vh [BATCH * DIM],     g_vl [BATCH * DIM];
__device__ __half g_bh [BATCH * 4 * DIM], g_bl [BATCH * 4 * DIM];
#define WTOT 48234496ull
__device__ __half g_w[WTOT];

__device__ __forceinline__ uint32_t smem_u32(const void* p) {
    uint32_t a;
    asm("{ .reg .u64 t; cvta.to.shared.u64 t, %1; cvt.u32.u64 %0, t; }" : "=r"(a) : "l"(p));
    return a;
}
__device__ __forceinline__ void ldsm4(uint32_t* r, uint32_t a) {
    asm volatile("ldmatrix.sync.aligned.m8n8.x4.shared.b16 {%0,%1,%2,%3}, [%4];"
                 : "=r"(r[0]), "=r"(r[1]), "=r"(r[2]), "=r"(r[3]) : "r"(a));
}
__device__ __forceinline__ void mma16816(float* c, const uint32_t* a, const uint32_t* b) {
    asm volatile("mma.sync.aligned.m16n8k16.row.col.f32.f16.f16.f32 "
                 "{%0,%1,%2,%3}, {%4,%5,%6,%7}, {%8,%9}, {%0,%1,%2,%3};"
                 : "+f"(c[0]), "+f"(c[1]), "+f"(c[2]), "+f"(c[3])
                 : "r"(a[0]), "r"(a[1]), "r"(a[2]), "r"(a[3]), "r"(b[0]), "r"(b[1]));
}
__device__ __forceinline__ void split1(float a, __half& h, __half& l) {
    h = __float2half_rn(a);
    l = __float2half_rn(a - __half2float(h));
}
__device__ __forceinline__ uint32_t pack2(__half a, __half b) {
    return (uint32_t)__half_as_ushort(a) | ((uint32_t)__half_as_ushort(b) << 16);
}
__device__ __forceinline__ float gelu1(float v) {
    return 0.5f * v * (1.f + erff(v * 0.70710678118654752f));
}

// ---- GEMM: C[M,N] = A[M,K] @ W[N,K]^T, A=(ah+al) fp16 split, W fp16 ----
// CTA 128x256, 16 warps (4m x 4n), warp tile 32x64, BK=64, 3-stage cp.async.
#define BM 128
#define BN 256
#define OAH 0
#define OAL 16384
#define OW  32768
#define STG 65536
#define NSTAGE 3
#define SMEMSZ (NSTAGE * STG)
#define NTHR 512

__device__ __forceinline__ void ld_tile(uint32_t tb, const __half* __restrict__ g,
                                        int row0, int K, int k0, int nrows, int tid) {
    const char* base = (const char*)(g + (size_t)row0 * K + k0);
    const size_t rs = (size_t)K * 2;
    #pragma unroll
    for (int i = tid; i < nrows * 8; i += NTHR) {
        int r = i >> 3, c2 = i & 7;
        uint32_t off = (uint32_t)(r * 128 + c2 * 16);
        uint32_t dst = tb + (off ^ ((off >> 3) & 0x70));
        asm volatile("cp.async.cg.shared.global [%0], [%1], 16;"
                     :: "r"(dst), "l"(base + (size_t)r * rs + c2 * 16));
    }
}
__device__ __forceinline__ void load_stage(uint32_t sb, int s,
    const __half* Ah, const __half* Al, const __half* W,
    int bm, int bn, int K, int c, int tid) {
    uint32_t st = sb + (uint32_t)s * STG;
    ld_tile(st + OAH, Ah, bm, K, c * 64, 128, tid);
    ld_tile(st + OAL, Al, bm, K, c * 64, 128, tid);
    ld_tile(st + OW,  W,  bn, K, c * 64, 256, tid);
    asm volatile("cp.async.commit_group;" ::: "memory");
}

template<int EP>
__global__ void __launch_bounds__(NTHR, 1)
gemm_tc(const __half* __restrict__ Ah, const __half* __restrict__ Al,
        const __half* __restrict__ W,
        const float* __restrict__ bias, const float* __restrict__ extra,
        float* __restrict__ Cf, __half* __restrict__ Oh, __half* __restrict__ Ol,
        int N, int K)
{
    extern __shared__ __align__(1024) char smem[];
    uint32_t sb = smem_u32(smem);
    const int tid = threadIdx.x, lane = tid & 31, wid = tid >> 5;
    const int bm = blockIdx.y * BM, bn = blockIdx.x * BN;
    const int wm = (wid & 3) * 32, wn = (wid >> 2) * 64;

    float acc[2][8][4] = {};

    const int arow = (lane & 7) + ((lane >> 3) & 1) * 8;
    const int ac   = (lane >> 4) & 1;
    const uint32_t axor = (uint32_t)((arow & 7) << 4);
    uint32_t aterm[2];
    #pragma unroll
    for (int mt = 0; mt < 2; mt++) aterm[mt] = (uint32_t)((wm + mt * 16 + arow) * 128);

    const int brow = lane & 7;
    const int bk   = (lane >> 3) & 1;
    const int bn8  = (lane >> 4) & 1;
    const uint32_t bxor = (uint32_t)(brow << 4);
    uint32_t bterm[4];
    #pragma unroll
    for (int ntp = 0; ntp < 4; ntp++)
        bterm[ntp] = (uint32_t)((wn + ntp * 16 + bn8 * 8 + brow) * 128);

    const int nch = K >> 6;
    load_stage(sb, 0, Ah, Al, W, bm, bn, K, 0, tid);
    load_stage(sb, 1, Ah, Al, W, bm, bn, K, 1, tid);

    for (int c = 0; c < nch; c++) {
        asm volatile("cp.async.wait_group 1;" ::: "memory");
        __syncthreads();
        if (c + 2 < nch) load_stage(sb, (c + 2) % NSTAGE, Ah, Al, W, bm, bn, K, c + 2, tid);
        else             asm volatile("cp.async.commit_group;" ::: "memory");

        uint32_t st = sb + (uint32_t)(c % NSTAGE) * STG;
        #pragma unroll
        for (int ks = 0; ks < 4; ks++) {
            const uint32_t ka = (uint32_t)(ks * 32 + ac * 16);
            const uint32_t kb = (uint32_t)(ks * 32 + bk * 16);
            uint32_t fb[8][2];
            #pragma unroll
            for (int ntp = 0; ntp < 4; ntp++)
                ldsm4(&fb[2 * ntp][0], st + OW + bterm[ntp] + (kb ^ bxor));
            #pragma unroll
            for (int mt = 0; mt < 2; mt++) {
                uint32_t fh[4], fl[4];
                ldsm4(fh, st + OAH + aterm[mt] + (ka ^ axor));
                ldsm4(fl, st + OAL + aterm[mt] + (ka ^ axor));
                #pragma unroll
                for (int nt = 0; nt < 8; nt++) {
                    mma16816(acc[mt][nt], fh, fb[nt]);
                    mma16816(acc[mt][nt], fl, fb[nt]);
                }
            }
        }
    }

    const int r0b = bm + wm + (lane >> 2);
    const int c0b = bn + wn + 2 * (lane & 3);
    #pragma unroll
    for (int mt = 0; mt < 2; mt++) {
        const int row0 = r0b + mt * 16, row1 = row0 + 8;
        #pragma unroll
        for (int nt = 0; nt < 8; nt++) {
            const int col = c0b + nt * 8;
            const float b0 = bias[col], b1 = bias[col + 1];
            float v00 = acc[mt][nt][0] + b0, v01 = acc[mt][nt][1] + b1;
            float v10 = acc[mt][nt][2] + b0, v11 = acc[mt][nt][3] + b1;
            const size_t g0 = (size_t)row0 * N + col, g1 = (size_t)row1 * N + col;

            if (EP == EP_GELUSP) {
                v00 = gelu1(v00); v01 = gelu1(v01); v10 = gelu1(v10); v11 = gelu1(v11);
            }
            if (EP == EP_SPLIT || EP == EP_GELUSP) {
                __half h0,l0,h1,l1;
                split1(v00,h0,l0); split1(v01,h1,l1);
                *(uint32_t*)(Oh + g0) = pack2(h0,h1);
                *(uint32_t*)(Ol + g0) = pack2(l0,l1);
                split1(v10,h0,l0); split1(v11,h1,l1);
                *(uint32_t*)(Oh + g1) = pack2(h0,h1);
                *(uint32_t*)(Ol + g1) = pack2(l0,l1);
            } else if (EP == EP_RESID) {
                float2 t0 = *(float2*)(Cf + g0);
                float2 t1 = *(float2*)(Cf + g1);
                t0.x += v00; t0.y += v01; t1.x += v10; t1.y += v11;
                *(float2*)(Cf + g0) = t0;
                *(float2*)(Cf + g1) = t1;
            } else if (EP == EP_ADD) {
                float2 e0 = *(const float2*)(extra + g0);
                float2 e1 = *(const float2*)(extra + g1);
                *(float2*)(Cf + g0) = make_float2(v00 + e0.x, v01 + e0.y);
                *(float2*)(Cf + g1) = make_float2(v10 + e1.x, v11 + e1.y);
            } else {
                *(float2*)(Cf + g0) = make_float2(v00, v01);
                *(float2*)(Cf + g1) = make_float2(v10, v11);
            }
        }
    }
}

// ---- elementwise ----
__global__ void cvt_k(const float* __restrict__ s, __half* __restrict__ o, int n) {
    int i = (blockIdx.x * blockDim.x + threadIdx.x) * 4;
    if (i >= n) return;
    float4 v = *(const float4*)(s + i);
    *(uint2*)(o + i) = make_uint2(pack2(__float2half_rn(v.x), __float2half_rn(v.y)),
                                  pack2(__float2half_rn(v.z), __float2half_rn(v.w)));
}
template<int SILU>
__global__ void split_k(const float* __restrict__ s, __half* __restrict__ oh,
                        __half* __restrict__ ol, int n) {
    int i = (blockIdx.x * blockDim.x + threadIdx.x) * 4;
    if (i >= n) return;
    float4 v = *(const float4*)(s + i);
    if (SILU) {
        v.x /= (1.f + expf(-v.x)); v.y /= (1.f + expf(-v.y));
        v.z /= (1.f + expf(-v.z)); v.w /= (1.f + expf(-v.w));
    }
    __half h0,h1,h2,h3,l0,l1,l2,l3;
    split1(v.x,h0,l0); split1(v.y,h1,l1); split1(v.z,h2,l2); split1(v.w,h3,l3);
    *(uint2*)(oh + i) = make_uint2(pack2(h0,h1), pack2(h2,h3));
    *(uint2*)(ol + i) = make_uint2(pack2(l0,l1), pack2(l2,l3));
}

// layernorm + adaLN modulation (ada has row stride 16*DIM now)
__global__ __launch_bounds__(256) void ln_split_k(
    const float* __restrict__ h, const float* __restrict__ g,
    const float* __restrict__ b, const float* __restrict__ ada,
    int so, int sho, __half* __restrict__ oh, __half* __restrict__ ol)
{
    const int row = blockIdx.x, t = threadIdx.x;
    float4 v = ((const float4*)(h + (size_t)row * DIM))[t];
    float s = v.x + v.y + v.z + v.w;
    float q = v.x*v.x + v.y*v.y + v.z*v.z + v.w*v.w;
    #pragma unroll
    for (int o = 16; o; o >>= 1) {
        s += __shfl_xor_sync(0xffffffffu, s, o);
        q += __shfl_xor_sync(0xffffffffu, q, o);
    }
    __shared__ float ss[8], qs[8];
    if ((t & 31) == 0) { ss[t >> 5] = s; qs[t >> 5] = q; }
    __syncthreads();
    s = 0.f; q = 0.f;
    #pragma unroll
    for (int i = 0; i < 8; i++) { s += ss[i]; q += qs[i]; }
    const float m = s * (1.f / DIM);
    const float inv = rsqrtf(q * (1.f / DIM) - m * m + 1e-5f);
    const int c = t * 4;
    float o0 = (v.x - m) * inv * g[c+0] + b[c+0];
    float o1 = (v.y - m) * inv * g[c+1] + b[c+1];
    float o2 = (v.z - m) * inv * g[c+2] + b[c+2];
    float o3 = (v.w - m) * inv * g[c+3] + b[c+3];
    if (ada) {
        const float* ar = ada + (size_t)row * (16 * DIM);
        o0 = o0 * (1.f + ar[so+c+0]) + ar[sho+c+0];
        o1 = o1 * (1.f + ar[so+c+1]) + ar[sho+c+1];
        o2 = o2 * (1.f + ar[so+c+2]) + ar[sho+c+2];
        o3 = o3 * (1.f + ar[so+c+3]) + ar[sho+c+3];
    }
    __half h0,h1,h2,h3,l0,l1,l2,l3;
    split1(o0,h0,l0); split1(o1,h1,l1); split1(o2,h2,l2); split1(o3,h3,l3);
    *(uint2*)(oh + (size_t)row * DIM + c) = make_uint2(pack2(h0,h1), pack2(h2,h3));
    *(uint2*)(ol + (size_t)row * DIM + c) = make_uint2(pack2(l0,l1), pack2(l2,l3));
}

// ---- launch ----
extern "C" void kernel_launch(void* const* d_in, const int* in_sizes, int n_in,
                              void* d_out, int out_size)
{
    const float* x        = (const float*)d_in[0];
    const float* t_emb    = (const float*)d_in[1];
    const float* condition= (const float*)d_in[2];
    const float* in_w     = (const float*)d_in[3];
    const float* in_b     = (const float*)d_in[4];
    const float* ln1_g    = (const float*)d_in[5];
    const float* ln1_b    = (const float*)d_in[6];
    const float* wqkv     = (const float*)d_in[7];
    const float* bqkv     = (const float*)d_in[8];
    const float* wo       = (const float*)d_in[9];
    const float* bo       = (const float*)d_in[10];
    const float* ln2_g    = (const float*)d_in[11];
    const float* ln2_b    = (const float*)d_in[12];
    const float* w1       = (const float*)d_in[13];
    const float* b1       = (const float*)d_in[14];
    const float* w2       = (const float*)d_in[15];
    const float* b2       = (const float*)d_in[16];
    const float* ada_w    = (const float*)d_in[17];
    const float* ada_b    = (const float*)d_in[18];
    const float* out_ln_g = (const float*)d_in[19];
    const float* out_ln_b = (const float*)d_in[20];
    const float* out_w    = (const float*)d_in[21];
    const float* out_b    = (const float*)d_in[22];

    float *h, *ada;
    __half *xnh,*xnl,*sth,*stl,*vh,*vl,*bh,*bl,*w;
    cudaGetSymbolAddress((void**)&h,   g_h);
    cudaGetSymbolAddress((void**)&ada, g_ada);
    cudaGetSymbolAddress((void**)&xnh, g_xnh); cudaGetSymbolAddress((void**)&xnl, g_xnl);
    cudaGetSymbolAddress((void**)&sth, g_sth); cudaGetSymbolAddress((void**)&stl, g_stl);
    cudaGetSymbolAddress((void**)&vh,  g_vh);  cudaGetSymbolAddress((void**)&vl,  g_vl);
    cudaGetSymbolAddress((void**)&bh,  g_bh);  cudaGetSymbolAddress((void**)&bl,  g_bl);
    cudaGetSymbolAddress((void**)&w,   g_w);

    cudaFuncSetAttribute(gemm_tc<EP_BIAS>,   cudaFuncAttributeMaxDynamicSharedMemorySize, SMEMSZ);
    cudaFuncSetAttribute(gemm_tc<EP_ADD>,    cudaFuncAttributeMaxDynamicSharedMemorySize, SMEMSZ);
    cudaFuncSetAttribute(gemm_tc<EP_RESID>,  cudaFuncAttributeMaxDynamicSharedMemorySize, SMEMSZ);
    cudaFuncSetAttribute(gemm_tc<EP_SPLIT>,  cudaFuncAttributeMaxDynamicSharedMemorySize, SMEMSZ);
    cudaFuncSetAttribute(gemm_tc<EP_GELUSP>, cudaFuncAttributeMaxDynamicSharedMemorySize, SMEMSZ);

    const size_t D2 = (size_t)DIM * DIM;
    // weight layout: [in 1][ada 4][v x4 4][wo x4 4][w1 x4 16][w2 x4 16][out 1] (units of D2)
    const size_t OFF_ADA = D2, OFF_V = 5 * D2, OFF_WO = 9 * D2,
                 OFF_W1 = 13 * D2, OFF_W2 = 29 * D2, OFF_OUT = 45 * D2;

    const int sb = 256;
    auto cvt = [&](const float* src, __half* o, size_t n) {
        cvt_k<<<(int)((n / 4 + sb - 1) / sb), sb>>>(src, o, (int)n);
    };

    split_k<0><<<(BATCH * DIM / 4 + sb - 1) / sb, sb>>>(x, xnh, xnl, BATCH * DIM);
    split_k<1><<<(BATCH * TEMB / 4 + sb - 1) / sb, sb>>>(t_emb, sth, stl, BATCH * TEMB);
    cvt(in_w,  w,           D2);
    cvt(ada_w, w + OFF_ADA, 4 * D2);          // [L,4D,TE] contiguous = [16384,256]
    for (int l = 0; l < NL; l++)
        cvt(wqkv + (size_t)l * 3 * D2 + 2 * D2, w + OFF_V + (size_t)l * D2, D2);
    cvt(wo, w + OFF_WO, 4 * D2);
    cvt(w1, w + OFF_W1, 16 * D2);
    cvt(w2, w + OFF_W2, 16 * D2);
    cvt(out_w, w + OFF_OUT, D2);

    const dim3 blk(NTHR);
    const dim3 gD  (DIM / BN, BATCH / BM);       // (4, 32)
    const dim3 g4D (4 * DIM / BN, BATCH / BM);   // (16, 32)
    const dim3 gAda(16 * DIM / BN, BATCH / BM);  // (64, 32)

    // one fused ada GEMM for all layers: [4096,16384] = st @ ada_w^T + ada_b
    gemm_tc<EP_BIAS><<<gAda, blk, SMEMSZ>>>(sth, stl, w + OFF_ADA, ada_b, nullptr,
                                            ada, nullptr, nullptr, 16 * DIM, TEMB);
    // h = x @ in_w^T + in_b + condition
    gemm_tc<EP_ADD><<<gD, blk, SMEMSZ>>>(xnh, xnl, w, in_b, condition, h, nullptr, nullptr, DIM, DIM);

    for (int l = 0; l < NL; l++) {
        const int ao = l * 4 * DIM;
        ln_split_k<<<BATCH, 256>>>(h, ln1_g + (size_t)l * DIM, ln1_b + (size_t)l * DIM,
                                   ada, ao, ao + DIM, xnh, xnl);
        gemm_tc<EP_SPLIT><<<gD, blk, SMEMSZ>>>(xnh, xnl, w + OFF_V + (size_t)l * D2,
                                               bqkv + (size_t)l * 3 * DIM + 2 * DIM, nullptr,
                                               nullptr, vh, vl, DIM, DIM);
        gemm_tc<EP_RESID><<<gD, blk, SMEMSZ>>>(vh, vl, w + OFF_WO + (size_t)l * D2,
                                               bo + (size_t)l * DIM, nullptr, h, nullptr, nullptr, DIM, DIM);
        ln_split_k<<<BATCH, 256>>>(h, ln2_g + (size_t)l * DIM, ln2_b + (size_t)l * DIM,
                                   ada, ao + 2 * DIM, ao + 3 * DIM, xnh, xnl);
        gemm_tc<EP_GELUSP><<<g4D, blk, SMEMSZ>>>(xnh, xnl, w + OFF_W1 + (size_t)l * 4 * D2,
                                                 b1 + (size_t)l * 4 * DIM, nullptr,
                                                 nullptr, bh, bl, 4 * DIM, DIM);
        gemm_tc<EP_RESID><<<gD, blk, SMEMSZ>>>(bh, bl, w + OFF_W2 + (size_t)l * 4 * D2,
                                               b2 + (size_t)l * DIM, nullptr, h, nullptr, nullptr, DIM, 4 * DIM);
    }

    ln_split_k<<<BATCH, 256>>>(h, out_ln_g, out_ln_b, nullptr, 0, 0, xnh, xnl);
    gemm_tc<EP_BIAS><<<gD, blk, SMEMSZ>>>(xnh, xnl, w + OFF_OUT, out_b, nullptr,
                                          (float*)d_out, nullptr, nullptr, DIM, DIM);
}

// round 7
// speedup vs baseline: 4.0481x; 1.0867x over previous
#include <cuda_runtime.h>
#include <cuda_fp16.h>
#include <math.h>
#include <stdint.h>

#define BATCH 4096
#define DIM   1024
#define TEMB  256
#define NL    4
#define D2    ((size_t)DIM * DIM)

#define EP_BIAS   0
#define EP_ADD    1
#define EP_RESID  2
#define EP_GELUSP 4
#define EP_HALF   5

__device__ float g_h  [BATCH * DIM];
__device__ float g_ada[(size_t)BATCH * 16 * DIM];
__device__ float g_bp [NL * DIM];            // fused attn bias b' = wo@bv + bo
__device__ float g_zero[16 * DIM];           // zero bias (device globals are 0-init)
__device__ __half g_xnh[BATCH * DIM],     g_xnl[BATCH * DIM];
__device__ __half g_sth[BATCH * TEMB],    g_stl[BATCH * TEMB];
__device__ __half g_bh [BATCH * 4 * DIM], g_bl [BATCH * 4 * DIM];
__device__ __half g_woh[NL * D2], g_wol[NL * D2];   // wo split (A of W' GEMM)
__device__ __half g_wvt[NL * D2];                   // wv transposed, fp16
__device__ __half g_wp [NL * D2];                   // W' = wo @ wv, fp16
#define WTOT (38 * D2)   // in(1) + ada(4) + w1(16) + w2(16) + out(1)
__device__ __half g_w[WTOT];

__device__ __forceinline__ uint32_t smem_u32(const void* p) {
    uint32_t a;
    asm("{ .reg .u64 t; cvta.to.shared.u64 t, %1; cvt.u32.u64 %0, t; }" : "=r"(a) : "l"(p));
    return a;
}
__device__ __forceinline__ void ldsm4(uint32_t* r, uint32_t a) {
    asm volatile("ldmatrix.sync.aligned.m8n8.x4.shared.b16 {%0,%1,%2,%3}, [%4];"
                 : "=r"(r[0]), "=r"(r[1]), "=r"(r[2]), "=r"(r[3]) : "r"(a));
}
__device__ __forceinline__ void mma16816(float* c, const uint32_t* a, const uint32_t* b) {
    asm volatile("mma.sync.aligned.m16n8k16.row.col.f32.f16.f16.f32 "
                 "{%0,%1,%2,%3}, {%4,%5,%6,%7}, {%8,%9}, {%0,%1,%2,%3};"
                 : "+f"(c[0]), "+f"(c[1]), "+f"(c[2]), "+f"(c[3])
                 : "r"(a[0]), "r"(a[1]), "r"(a[2]), "r"(a[3]), "r"(b[0]), "r"(b[1]));
}
__device__ __forceinline__ void split1(float a, __half& h, __half& l) {
    h = __float2half_rn(a);
    l = __float2half_rn(a - __half2float(h));
}
__device__ __forceinline__ uint32_t pack2(__half a, __half b) {
    return (uint32_t)__half_as_ushort(a) | ((uint32_t)__half_as_ushort(b) << 16);
}
__device__ __forceinline__ float gelu1(float v) {
    return 0.5f * v * (1.f + erff(v * 0.70710678118654752f));
}

// ---- GEMM: C[M,N] = A[M,K] @ W[N,K]^T, A=(ah[+al]) fp16, W fp16 ----
// CTA 128x256, 16 warps (4m x 4n), warp tile 32x64, BK=64, 3-stage cp.async.
#define BM 128
#define BN 256
#define OAH 0
#define OAL 16384
#define OW  32768
#define STG 65536
#define NSTAGE 3
#define SMEMSZ (NSTAGE * STG)
#define NTHR 512

__device__ __forceinline__ void ld_tile(uint32_t tb, const __half* __restrict__ g,
                                        int row0, int K, int k0, int nrows, int tid) {
    const char* base = (const char*)(g + (size_t)row0 * K + k0);
    const size_t rs = (size_t)K * 2;
    #pragma unroll
    for (int i = tid; i < nrows * 8; i += NTHR) {
        int r = i >> 3, c2 = i & 7;
        uint32_t off = (uint32_t)(r * 128 + c2 * 16);
        uint32_t dst = tb + (off ^ ((off >> 3) & 0x70));
        asm volatile("cp.async.cg.shared.global [%0], [%1], 16;"
                     :: "r"(dst), "l"(base + (size_t)r * rs + c2 * 16));
    }
}
template<int NPASS>
__device__ __forceinline__ void load_stage(uint32_t sb, int s,
    const __half* Ah, const __half* Al, const __half* W,
    int bm, int bn, int K, int c, int tid) {
    uint32_t st = sb + (uint32_t)s * STG;
    ld_tile(st + OAH, Ah, bm, K, c * 64, 128, tid);
    if (NPASS == 2) ld_tile(st + OAL, Al, bm, K, c * 64, 128, tid);
    ld_tile(st + OW, W, bn, K, c * 64, 256, tid);
    asm volatile("cp.async.commit_group;" ::: "memory");
}

template<int EP, int NPASS>
__global__ void __launch_bounds__(NTHR, 1)
gemm_tc(const __half* __restrict__ Ah, const __half* __restrict__ Al,
        const __half* __restrict__ W,
        const float* __restrict__ bias, const float* __restrict__ extra,
        float* __restrict__ Cf, __half* __restrict__ Oh,
        int N, int K, size_t zA, size_t zW, size_t zC)
{
    extern __shared__ __align__(1024) char smem[];
    uint32_t sb = smem_u32(smem);
    const int tid = threadIdx.x, lane = tid & 31, wid = tid >> 5;
    const int bm = blockIdx.y * BM, bn = blockIdx.x * BN;
    const size_t z = blockIdx.z;
    Ah += z * zA; Al += z * zA; W += z * zW;

    float acc[2][8][4] = {};

    const int wm = (wid & 3) * 32, wn = (wid >> 2) * 64;
    const int arow = (lane & 7) + ((lane >> 3) & 1) * 8;
    const int ac   = (lane >> 4) & 1;
    const uint32_t axor = (uint32_t)((arow & 7) << 4);
    uint32_t aterm[2];
    #pragma unroll
    for (int mt = 0; mt < 2; mt++) aterm[mt] = (uint32_t)((wm + mt * 16 + arow) * 128);

    const int brow = lane & 7;
    const int bk   = (lane >> 3) & 1;
    const int bn8  = (lane >> 4) & 1;
    const uint32_t bxor = (uint32_t)(brow << 4);
    uint32_t bterm[4];
    #pragma unroll
    for (int ntp = 0; ntp < 4; ntp++)
        bterm[ntp] = (uint32_t)((wn + ntp * 16 + bn8 * 8 + brow) * 128);

    const int nch = K >> 6;
    load_stage<NPASS>(sb, 0, Ah, Al, W, bm, bn, K, 0, tid);
    load_stage<NPASS>(sb, 1, Ah, Al, W, bm, bn, K, 1, tid);

    for (int c = 0; c < nch; c++) {
        asm volatile("cp.async.wait_group 1;" ::: "memory");
        __syncthreads();
        if (c + 2 < nch) load_stage<NPASS>(sb, (c + 2) % NSTAGE, Ah, Al, W, bm, bn, K, c + 2, tid);
        else             asm volatile("cp.async.commit_group;" ::: "memory");

        uint32_t st = sb + (uint32_t)(c % NSTAGE) * STG;
        #pragma unroll
        for (int ks = 0; ks < 4; ks++) {
            const uint32_t ka = (uint32_t)(ks * 32 + ac * 16);
            const uint32_t kb = (uint32_t)(ks * 32 + bk * 16);
            uint32_t fb[8][2];
            #pragma unroll
            for (int ntp = 0; ntp < 4; ntp++)
                ldsm4(&fb[2 * ntp][0], st + OW + bterm[ntp] + (kb ^ bxor));
            #pragma unroll
            for (int mt = 0; mt < 2; mt++) {
                uint32_t fh[4], fl[4];
                ldsm4(fh, st + OAH + aterm[mt] + (ka ^ axor));
                if (NPASS == 2) ldsm4(fl, st + OAL + aterm[mt] + (ka ^ axor));
                #pragma unroll
                for (int nt = 0; nt < 8; nt++) {
                    mma16816(acc[mt][nt], fh, fb[nt]);
                    if (NPASS == 2) mma16816(acc[mt][nt], fl, fb[nt]);
                }
            }
        }
    }

    const int r0b = bm + wm + (lane >> 2);
    const int c0b = bn + wn + 2 * (lane & 3);
    #pragma unroll
    for (int mt = 0; mt < 2; mt++) {
        const int row0 = r0b + mt * 16, row1 = row0 + 8;
        #pragma unroll
        for (int nt = 0; nt < 8; nt++) {
            const int col = c0b + nt * 8;
            const float b0 = bias[col], b1 = bias[col + 1];
            float v00 = acc[mt][nt][0] + b0, v01 = acc[mt][nt][1] + b1;
            float v10 = acc[mt][nt][2] + b0, v11 = acc[mt][nt][3] + b1;
            const size_t g0 = z * zC + (size_t)row0 * N + col;
            const size_t g1 = z * zC + (size_t)row1 * N + col;

            if (EP == EP_GELUSP) {
                v00 = gelu1(v00); v01 = gelu1(v01); v10 = gelu1(v10); v11 = gelu1(v11);
            }
            if (EP == EP_GELUSP) {
                __half h0,l0,h1,l1;
                split1(v00,h0,l0); split1(v01,h1,l1);
                *(uint32_t*)(Oh + g0) = pack2(h0,h1);
                *(uint32_t*)(g_bl + g0) = pack2(l0,l1);
                split1(v10,h0,l0); split1(v11,h1,l1);
                *(uint32_t*)(Oh + g1) = pack2(h0,h1);
                *(uint32_t*)(g_bl + g1) = pack2(l0,l1);
            } else if (EP == EP_HALF) {
                *(uint32_t*)(Oh + g0) = pack2(__float2half_rn(v00), __float2half_rn(v01));
                *(uint32_t*)(Oh + g1) = pack2(__float2half_rn(v10), __float2half_rn(v11));
            } else if (EP == EP_RESID) {
                float2 t0 = *(float2*)(Cf + g0);
                float2 t1 = *(float2*)(Cf + g1);
                t0.x += v00; t0.y += v01; t1.x += v10; t1.y += v11;
                *(float2*)(Cf + g0) = t0;
                *(float2*)(Cf + g1) = t1;
            } else if (EP == EP_ADD) {
                float2 e0 = *(const float2*)(extra + g0);
                float2 e1 = *(const float2*)(extra + g1);
                *(float2*)(Cf + g0) = make_float2(v00 + e0.x, v01 + e0.y);
                *(float2*)(Cf + g1) = make_float2(v10 + e1.x, v11 + e1.y);
            } else {
                *(float2*)(Cf + g0) = make_float2(v00, v01);
                *(float2*)(Cf + g1) = make_float2(v10, v11);
            }
        }
    }
}

// ---- elementwise / small kernels ----
__global__ void cvt_k(const float* __restrict__ s, __half* __restrict__ o, int n) {
    int i = (blockIdx.x * blockDim.x + threadIdx.x) * 4;
    if (i >= n) return;
    float4 v = *(const float4*)(s + i);
    *(uint2*)(o + i) = make_uint2(pack2(__float2half_rn(v.x), __float2half_rn(v.y)),
                                  pack2(__float2half_rn(v.z), __float2half_rn(v.w)));
}
template<int SILU>
__global__ void split_k(const float* __restrict__ s, __half* __restrict__ oh,
                        __half* __restrict__ ol, int n) {
    int i = (blockIdx.x * blockDim.x + threadIdx.x) * 4;
    if (i >= n) return;
    float4 v = *(const float4*)(s + i);
    if (SILU) {
        v.x /= (1.f + expf(-v.x)); v.y /= (1.f + expf(-v.y));
        v.z /= (1.f + expf(-v.z)); v.w /= (1.f + expf(-v.w));
    }
    __half h0,h1,h2,h3,l0,l1,l2,l3;
    split1(v.x,h0,l0); split1(v.y,h1,l1); split1(v.z,h2,l2); split1(v.w,h3,l3);
    *(uint2*)(oh + i) = make_uint2(pack2(h0,h1), pack2(h2,h3));
    *(uint2*)(ol + i) = make_uint2(pack2(l0,l1), pack2(l2,l3));
}

// wvt[l][k][m] = wqkv[l][2D + m][k]  (fp32 -> fp16 transpose)
__global__ void transpose_wv(const float* __restrict__ wqkv, __half* __restrict__ wvt) {
    __shared__ float tile[32][33];
    const int l = blockIdx.z;
    const float* src = wqkv + (size_t)l * 3 * D2 + 2 * D2;
    __half* dst = wvt + (size_t)l * D2;
    const int k0 = blockIdx.x * 32, m0 = blockIdx.y * 32;
    const int tx = threadIdx.x, ty = threadIdx.y;   // 32 x 8
    #pragma unroll
    for (int i = 0; i < 4; i++) {
        int r = ty + i * 8;
        tile[r][tx] = src[(size_t)(m0 + r) * DIM + k0 + tx];
    }
    __syncthreads();
    #pragma unroll
    for (int i = 0; i < 4; i++) {
        int r = ty + i * 8;
        dst[(size_t)(k0 + r) * DIM + m0 + tx] = __float2half_rn(tile[tx][r]);
    }
}

// b'[l][n] = bo[l][n] + sum_k wo[l][n][k] * bqkv[l][2D + k]
__global__ __launch_bounds__(256) void bprime_k(
    const float* __restrict__ wo, const float* __restrict__ bqkv,
    const float* __restrict__ bo, float* __restrict__ bp)
{
    const int n = blockIdx.x, l = blockIdx.y, t = threadIdx.x;
    const float* wr = wo + (size_t)l * D2 + (size_t)n * DIM;
    const float* bv = bqkv + (size_t)l * 3 * DIM + 2 * DIM;
    float s = 0.f;
    for (int k = t; k < DIM; k += 256) s += wr[k] * bv[k];
    #pragma unroll
    for (int o = 16; o; o >>= 1) s += __shfl_xor_sync(0xffffffffu, s, o);
    __shared__ float ss[8];
    if ((t & 31) == 0) ss[t >> 5] = s;
    __syncthreads();
    if (t == 0) {
        float r = 0.f;
        #pragma unroll
        for (int i = 0; i < 8; i++) r += ss[i];
        bp[l * DIM + n] = r + bo[l * DIM + n];
    }
}

__global__ __launch_bounds__(256) void ln_split_k(
    const float* __restrict__ h, const float* __restrict__ g,
    const float* __restrict__ b, const float* __restrict__ ada,
    int so, int sho, __half* __restrict__ oh, __half* __restrict__ ol)
{
    const int row = blockIdx.x, t = threadIdx.x;
    float4 v = ((const float4*)(h + (size_t)row * DIM))[t];
    float s = v.x + v.y + v.z + v.w;
    float q = v.x*v.x + v.y*v.y + v.z*v.z + v.w*v.w;
    #pragma unroll
    for (int o = 16; o; o >>= 1) {
        s += __shfl_xor_sync(0xffffffffu, s, o);
        q += __shfl_xor_sync(0xffffffffu, q, o);
    }
    __shared__ float ss[8], qs[8];
    if ((t & 31) == 0) { ss[t >> 5] = s; qs[t >> 5] = q; }
    __syncthreads();
    s = 0.f; q = 0.f;
    #pragma unroll
    for (int i = 0; i < 8; i++) { s += ss[i]; q += qs[i]; }
    const float m = s * (1.f / DIM);
    const float inv = rsqrtf(q * (1.f / DIM) - m * m + 1e-5f);
    const int c = t * 4;
    float o0 = (v.x - m) * inv * g[c+0] + b[c+0];
    float o1 = (v.y - m) * inv * g[c+1] + b[c+1];
    float o2 = (v.z - m) * inv * g[c+2] + b[c+2];
    float o3 = (v.w - m) * inv * g[c+3] + b[c+3];
    if (ada) {
        const float* ar = ada + (size_t)row * (16 * DIM);
        o0 = o0 * (1.f + ar[so+c+0]) + ar[sho+c+0];
        o1 = o1 * (1.f + ar[so+c+1]) + ar[sho+c+1];
        o2 = o2 * (1.f + ar[so+c+2]) + ar[sho+c+2];
        o3 = o3 * (1.f + ar[so+c+3]) + ar[sho+c+3];
    }
    __half h0,h1,h2,h3,l0,l1,l2,l3;
    split1(o0,h0,l0); split1(o1,h1,l1); split1(o2,h2,l2); split1(o3,h3,l3);
    *(uint2*)(oh + (size_t)row * DIM + c) = make_uint2(pack2(h0,h1), pack2(h2,h3));
    *(uint2*)(ol + (size_t)row * DIM + c) = make_uint2(pack2(l0,l1), pack2(l2,l3));
}

// ---- launch ----
extern "C" void kernel_launch(void* const* d_in, const int* in_sizes, int n_in,
                              void* d_out, int out_size)
{
    const float* x        = (const float*)d_in[0];
    const float* t_emb    = (const float*)d_in[1];
    const float* condition= (const float*)d_in[2];
    const float* in_w     = (const float*)d_in[3];
    const float* in_b     = (const float*)d_in[4];
    const float* ln1_g    = (const float*)d_in[5];
    const float* ln1_b    = (const float*)d_in[6];
    const float* wqkv     = (const float*)d_in[7];
    const float* bqkv     = (const float*)d_in[8];
    const float* wo       = (const float*)d_in[9];
    const float* bo       = (const float*)d_in[10];
    const float* ln2_g    = (const float*)d_in[11];
    const float* ln2_b    = (const float*)d_in[12];
    const float* w1       = (const float*)d_in[13];
    const float* b1       = (const float*)d_in[14];
    const float* w2       = (const float*)d_in[15];
    const float* b2       = (const float*)d_in[16];
    const float* ada_w    = (const float*)d_in[17];
    const float* ada_b    = (const float*)d_in[18];
    const float* out_ln_g = (const float*)d_in[19];
    const float* out_ln_b = (const float*)d_in[20];
    const float* out_w    = (const float*)d_in[21];
    const float* out_b    = (const float*)d_in[22];

    float *h, *ada, *bp, *zero;
    __half *xnh,*xnl,*sth,*stl,*bh,*bl,*w,*woh,*wol,*wvt,*wp;
    cudaGetSymbolAddress((void**)&h,   g_h);
    cudaGetSymbolAddress((void**)&ada, g_ada);
    cudaGetSymbolAddress((void**)&bp,  g_bp);
    cudaGetSymbolAddress((void**)&zero,g_zero);
    cudaGetSymbolAddress((void**)&xnh, g_xnh); cudaGetSymbolAddress((void**)&xnl, g_xnl);
    cudaGetSymbolAddress((void**)&sth, g_sth); cudaGetSymbolAddress((void**)&stl, g_stl);
    cudaGetSymbolAddress((void**)&bh,  g_bh);  cudaGetSymbolAddress((void**)&bl,  g_bl);
    cudaGetSymbolAddress((void**)&w,   g_w);
    cudaGetSymbolAddress((void**)&woh, g_woh); cudaGetSymbolAddress((void**)&wol, g_wol);
    cudaGetSymbolAddress((void**)&wvt, g_wvt); cudaGetSymbolAddress((void**)&wp,  g_wp);

    cudaFuncSetAttribute(gemm_tc<EP_BIAS,1>,   cudaFuncAttributeMaxDynamicSharedMemorySize, SMEMSZ);
    cudaFuncSetAttribute(gemm_tc<EP_BIAS,2>,   cudaFuncAttributeMaxDynamicSharedMemorySize, SMEMSZ);
    cudaFuncSetAttribute(gemm_tc<EP_ADD,2>,    cudaFuncAttributeMaxDynamicSharedMemorySize, SMEMSZ);
    cudaFuncSetAttribute(gemm_tc<EP_RESID,2>,  cudaFuncAttributeMaxDynamicSharedMemorySize, SMEMSZ);
    cudaFuncSetAttribute(gemm_tc<EP_GELUSP,2>, cudaFuncAttributeMaxDynamicSharedMemorySize, SMEMSZ);
    cudaFuncSetAttribute(gemm_tc<EP_HALF,2>,   cudaFuncAttributeMaxDynamicSharedMemorySize, SMEMSZ);

    // weight layout in g_w (units of D2): in @0, ada @1 (4), w1 @5 (16), w2 @21 (16), out @37
    const size_t OFF_ADA = D2, OFF_W1 = 5 * D2, OFF_W2 = 21 * D2, OFF_OUT = 37 * D2;

    const int sb = 256;
    auto cvt = [&](const float* src, __half* o, size_t n) {
        cvt_k<<<(int)((n / 4 + sb - 1) / sb), sb>>>(src, o, (int)n);
    };

    // conversions / precompute
    split_k<0><<<(BATCH * DIM / 4 + sb - 1) / sb, sb>>>(x, xnh, xnl, BATCH * DIM);
    split_k<1><<<(BATCH * TEMB / 4 + sb - 1) / sb, sb>>>(t_emb, sth, stl, BATCH * TEMB);
    cvt(in_w,  w,           D2);
    cvt(ada_w, w + OFF_ADA, 4 * D2);
    cvt(w1,    w + OFF_W1,  16 * D2);
    cvt(w2,    w + OFF_W2,  16 * D2);
    cvt(out_w, w + OFF_OUT, D2);
    split_k<0><<<(int)(4 * D2 / 4 + sb - 1) / sb, sb>>>(wo, woh, wol, (int)(4 * D2));
    transpose_wv<<<dim3(32, 32, NL), dim3(32, 8)>>>(wqkv, wvt);
    bprime_k<<<dim3(DIM, NL), 256>>>(wo, bqkv, bo, bp);

    const dim3 blk(NTHR);
    const dim3 gD  (DIM / BN, BATCH / BM);        // (4, 32)
    const dim3 g4D (4 * DIM / BN, BATCH / BM);    // (16, 32)
    const dim3 gAda(16 * DIM / BN, BATCH / BM);   // (64, 32)
    const dim3 gWp (DIM / BN, DIM / BM, NL);      // (4, 8, 4) batched W'

    // W'[l] = wo[l] @ wv[l]  (batched over layers)
    gemm_tc<EP_HALF,2><<<gWp, blk, SMEMSZ>>>(woh, wol, wvt, zero, nullptr,
                                             nullptr, wp, DIM, DIM, D2, D2, D2);
    // ada (1-pass) and input projection
    gemm_tc<EP_BIAS,1><<<gAda, blk, SMEMSZ>>>(sth, sth, w + OFF_ADA, ada_b, nullptr,
                                              ada, nullptr, 16 * DIM, TEMB, 0, 0, 0);
    gemm_tc<EP_ADD,2><<<gD, blk, SMEMSZ>>>(xnh, xnl, w, in_b, condition,
                                           h, nullptr, DIM, DIM, 0, 0, 0);

    for (int l = 0; l < NL; l++) {
        const int ao = l * 4 * DIM;
        ln_split_k<<<BATCH, 256>>>(h, ln1_g + (size_t)l * DIM, ln1_b + (size_t)l * DIM,
                                   ada, ao, ao + DIM, xnh, xnl);
        // h += xn @ W'^T + b'   (fused v+wo, attn==identity at seq_len 1)
        gemm_tc<EP_RESID,2><<<gD, blk, SMEMSZ>>>(xnh, xnl, wp + (size_t)l * D2,
                                                 bp + (size_t)l * DIM, nullptr,
                                                 h, nullptr, DIM, DIM, 0, 0, 0);
        ln_split_k<<<BATCH, 256>>>(h, ln2_g + (size_t)l * DIM, ln2_b + (size_t)l * DIM,
                                   ada, ao + 2 * DIM, ao + 3 * DIM, xnh, xnl);
        gemm_tc<EP_GELUSP,2><<<g4D, blk, SMEMSZ>>>(xnh, xnl, w + OFF_W1 + (size_t)l * 4 * D2,
                                                   b1 + (size_t)l * 4 * DIM, nullptr,
                                                   nullptr, bh, 4 * DIM, DIM, 0, 0, 0);
        gemm_tc<EP_RESID,2><<<gD, blk, SMEMSZ>>>(bh, bl, w + OFF_W2 + (size_t)l * 4 * D2,
                                                 b2 + (size_t)l * DIM, nullptr,
                                                 h, nullptr, DIM, 4 * DIM, 0, 0, 0);
    }

    ln_split_k<<<BATCH, 256>>>(h, out_ln_g, out_ln_b, nullptr, 0, 0, xnh, xnl);
    gemm_tc<EP_BIAS,2><<<gD, blk, SMEMSZ>>>(xnh, xnl, w + OFF_OUT, out_b, nullptr,
                                            (float*)d_out, nullptr, DIM, DIM, 0, 0, 0);
}

// round 8
// speedup vs baseline: 6.8143x; 1.6833x over previous
#include <cuda_runtime.h>
#include <cuda_fp16.h>
#include <math.h>
#include <stdint.h>

#define BATCH 4096
#define DIM   1024
#define TEMB  256
#define NL    4
#define D2    ((size_t)DIM * DIM)

#define EP_BIAS  0   // fp32 out
#define EP_ADD   1   // fp32 out + extra
#define EP_RESID 2   // fp32 accumulate
#define EP_GELUH 3   // gelu -> fp16 out
#define EP_HALF  4   // fp16 out

__device__ float g_h  [BATCH * DIM];
__device__ float g_ada[(size_t)BATCH * 16 * DIM];
__device__ float g_bp [NL * DIM];
__device__ float g_zero[16 * DIM];
__device__ __half g_xh [BATCH * DIM];          // fp16 activations (GEMM A)
__device__ __half g_st [BATCH * TEMB];         // silu(t_emb) fp16
__device__ __half g_big[BATCH * 4 * DIM];      // gelu output fp16
__device__ __half g_woh[NL * D2];              // wo fp16
__device__ __half g_wvt[NL * D2];              // wv^T fp16
__device__ __half g_wp [NL * D2];              // W' = wo @ wv fp16
#define WTOT (38 * D2)  // in(1) ada(4) w1(16) w2(16) out(1)
__device__ __half g_w[WTOT];

__device__ __forceinline__ uint32_t smem_u32(const void* p) {
    uint32_t a;
    asm("{ .reg .u64 t; cvta.to.shared.u64 t, %1; cvt.u32.u64 %0, t; }" : "=r"(a) : "l"(p));
    return a;
}
__device__ __forceinline__ void ldsm4(uint32_t* r, uint32_t a) {
    asm volatile("ldmatrix.sync.aligned.m8n8.x4.shared.b16 {%0,%1,%2,%3}, [%4];"
                 : "=r"(r[0]), "=r"(r[1]), "=r"(r[2]), "=r"(r[3]) : "r"(a));
}
__device__ __forceinline__ void mma16816(float* c, const uint32_t* a, const uint32_t* b) {
    asm volatile("mma.sync.aligned.m16n8k16.row.col.f32.f16.f16.f32 "
                 "{%0,%1,%2,%3}, {%4,%5,%6,%7}, {%8,%9}, {%0,%1,%2,%3};"
                 : "+f"(c[0]), "+f"(c[1]), "+f"(c[2]), "+f"(c[3])
                 : "r"(a[0]), "r"(a[1]), "r"(a[2]), "r"(a[3]), "r"(b[0]), "r"(b[1]));
}
__device__ __forceinline__ uint32_t pack2(__half a, __half b) {
    return (uint32_t)__half_as_ushort(a) | ((uint32_t)__half_as_ushort(b) << 16);
}
__device__ __forceinline__ float gelu1(float v) {
    return 0.5f * v * (1.f + erff(v * 0.70710678118654752f));
}

// ---- GEMM: C[M,N] = A[M,K] @ W[N,K]^T, fp16 in, fp32 accum ----
// CTA 128x256, 16 warps (4m x 4n), warp tile 32x64, BK=64, 4-stage cp.async.
#define BM 128
#define BN 256
#define OW  16384
#define STG 49152
#define NSTAGE 4
#define SMEMSZ (NSTAGE * STG)
#define NTHR 512

__device__ __forceinline__ void ld_tile(uint32_t tb, const __half* __restrict__ g,
                                        int row0, int K, int k0, int nrows, int tid) {
    const char* base = (const char*)(g + (size_t)row0 * K + k0);
    const size_t rs = (size_t)K * 2;
    #pragma unroll
    for (int i = tid; i < nrows * 8; i += NTHR) {
        int r = i >> 3, c2 = i & 7;
        uint32_t off = (uint32_t)(r * 128 + c2 * 16);
        uint32_t dst = tb + (off ^ ((off >> 3) & 0x70));
        asm volatile("cp.async.cg.shared.global [%0], [%1], 16;"
                     :: "r"(dst), "l"(base + (size_t)r * rs + c2 * 16));
    }
}
__device__ __forceinline__ void load_stage(uint32_t sb, int s,
    const __half* A, const __half* W, int bm, int bn, int K, int c, int tid) {
    uint32_t st = sb + (uint32_t)s * STG;
    ld_tile(st,      A, bm, K, c * 64, 128, tid);
    ld_tile(st + OW, W, bn, K, c * 64, 256, tid);
    asm volatile("cp.async.commit_group;" ::: "memory");
}

template<int EP>
__global__ void __launch_bounds__(NTHR, 1)
gemm_tc(const __half* __restrict__ A, const __half* __restrict__ W,
        const float* __restrict__ bias, const float* __restrict__ extra,
        float* __restrict__ Cf, __half* __restrict__ Oh,
        int N, int K, size_t zA, size_t zW, size_t zC)
{
    extern __shared__ __align__(1024) char smem[];
    uint32_t sb = smem_u32(smem);
    const int tid = threadIdx.x, lane = tid & 31, wid = tid >> 5;
    const int bm = blockIdx.y * BM, bn = blockIdx.x * BN;
    const size_t z = blockIdx.z;
    A += z * zA; W += z * zW;

    float acc[2][8][4] = {};

    const int wm = (wid & 3) * 32, wn = (wid >> 2) * 64;
    const int arow = (lane & 7) + ((lane >> 3) & 1) * 8;
    const int ac   = (lane >> 4) & 1;
    const uint32_t axor = (uint32_t)((arow & 7) << 4);
    uint32_t aterm[2];
    #pragma unroll
    for (int mt = 0; mt < 2; mt++) aterm[mt] = (uint32_t)((wm + mt * 16 + arow) * 128);

    const int brow = lane & 7;
    const int bk   = (lane >> 3) & 1;
    const int bn8  = (lane >> 4) & 1;
    const uint32_t bxor = (uint32_t)(brow << 4);
    uint32_t bterm[4];
    #pragma unroll
    for (int ntp = 0; ntp < 4; ntp++)
        bterm[ntp] = (uint32_t)((wn + ntp * 16 + bn8 * 8 + brow) * 128);

    const int nch = K >> 6;
    load_stage(sb, 0, A, W, bm, bn, K, 0, tid);
    load_stage(sb, 1, A, W, bm, bn, K, 1, tid);
    load_stage(sb, 2, A, W, bm, bn, K, 2, tid);

    for (int c = 0; c < nch; c++) {
        asm volatile("cp.async.wait_group 2;" ::: "memory");
        __syncthreads();
        if (c + 3 < nch) load_stage(sb, (c + 3) % NSTAGE, A, W, bm, bn, K, c + 3, tid);
        else             asm volatile("cp.async.commit_group;" ::: "memory");

        uint32_t st = sb + (uint32_t)(c % NSTAGE) * STG;
        #pragma unroll
        for (int ks = 0; ks < 4; ks++) {
            const uint32_t ka = (uint32_t)(ks * 32 + ac * 16);
            const uint32_t kb = (uint32_t)(ks * 32 + bk * 16);
            uint32_t fb[8][2];
            #pragma unroll
            for (int ntp = 0; ntp < 4; ntp++)
                ldsm4(&fb[2 * ntp][0], st + OW + bterm[ntp] + (kb ^ bxor));
            #pragma unroll
            for (int mt = 0; mt < 2; mt++) {
                uint32_t fa[4];
                ldsm4(fa, st + aterm[mt] + (ka ^ axor));
                #pragma unroll
                for (int nt = 0; nt < 8; nt++)
                    mma16816(acc[mt][nt], fa, fb[nt]);
            }
        }
    }

    const int r0b = bm + wm + (lane >> 2);
    const int c0b = bn + wn + 2 * (lane & 3);
    #pragma unroll
    for (int mt = 0; mt < 2; mt++) {
        const int row0 = r0b + mt * 16, row1 = row0 + 8;
        #pragma unroll
        for (int nt = 0; nt < 8; nt++) {
            const int col = c0b + nt * 8;
            const float b0 = bias[col], b1 = bias[col + 1];
            float v00 = acc[mt][nt][0] + b0, v01 = acc[mt][nt][1] + b1;
            float v10 = acc[mt][nt][2] + b0, v11 = acc[mt][nt][3] + b1;
            const size_t g0 = z * zC + (size_t)row0 * N + col;
            const size_t g1 = z * zC + (size_t)row1 * N + col;

            if (EP == EP_GELUH) {
                v00 = gelu1(v00); v01 = gelu1(v01); v10 = gelu1(v10); v11 = gelu1(v11);
            }
            if (EP == EP_GELUH || EP == EP_HALF) {
                *(uint32_t*)(Oh + g0) = pack2(__float2half_rn(v00), __float2half_rn(v01));
                *(uint32_t*)(Oh + g1) = pack2(__float2half_rn(v10), __float2half_rn(v11));
            } else if (EP == EP_RESID) {
                float2 t0 = *(float2*)(Cf + g0);
                float2 t1 = *(float2*)(Cf + g1);
                t0.x += v00; t0.y += v01; t1.x += v10; t1.y += v11;
                *(float2*)(Cf + g0) = t0;
                *(float2*)(Cf + g1) = t1;
            } else if (EP == EP_ADD) {
                float2 e0 = *(const float2*)(extra + g0);
                float2 e1 = *(const float2*)(extra + g1);
                *(float2*)(Cf + g0) = make_float2(v00 + e0.x, v01 + e0.y);
                *(float2*)(Cf + g1) = make_float2(v10 + e1.x, v11 + e1.y);
            } else {
                *(float2*)(Cf + g0) = make_float2(v00, v01);
                *(float2*)(Cf + g1) = make_float2(v10, v11);
            }
        }
    }
}

// ---- elementwise / small kernels ----
template<int SILU>
__global__ void cvt_k(const float* __restrict__ s, __half* __restrict__ o, int n) {
    int i = (blockIdx.x * blockDim.x + threadIdx.x) * 4;
    if (i >= n) return;
    float4 v = *(const float4*)(s + i);
    if (SILU) {
        v.x /= (1.f + expf(-v.x)); v.y /= (1.f + expf(-v.y));
        v.z /= (1.f + expf(-v.z)); v.w /= (1.f + expf(-v.w));
    }
    *(uint2*)(o + i) = make_uint2(pack2(__float2half_rn(v.x), __float2half_rn(v.y)),
                                  pack2(__float2half_rn(v.z), __float2half_rn(v.w)));
}

__global__ void transpose_wv(const float* __restrict__ wqkv, __half* __restrict__ wvt) {
    __shared__ float tile[32][33];
    const int l = blockIdx.z;
    const float* src = wqkv + (size_t)l * 3 * D2 + 2 * D2;
    __half* dst = wvt + (size_t)l * D2;
    const int k0 = blockIdx.x * 32, m0 = blockIdx.y * 32;
    const int tx = threadIdx.x, ty = threadIdx.y;
    #pragma unroll
    for (int i = 0; i < 4; i++) {
        int r = ty + i * 8;
        tile[r][tx] = src[(size_t)(m0 + r) * DIM + k0 + tx];
    }
    __syncthreads();
    #pragma unroll
    for (int i = 0; i < 4; i++) {
        int r = ty + i * 8;
        dst[(size_t)(k0 + r) * DIM + m0 + tx] = __float2half_rn(tile[tx][r]);
    }
}

__global__ __launch_bounds__(256) void bprime_k(
    const float* __restrict__ wo, const float* __restrict__ bqkv,
    const float* __restrict__ bo, float* __restrict__ bp)
{
    const int n = blockIdx.x, l = blockIdx.y, t = threadIdx.x;
    const float* wr = wo + (size_t)l * D2 + (size_t)n * DIM;
    const float* bv = bqkv + (size_t)l * 3 * DIM + 2 * DIM;
    float s = 0.f;
    for (int k = t; k < DIM; k += 256) s += wr[k] * bv[k];
    #pragma unroll
    for (int o = 16; o; o >>= 1) s += __shfl_xor_sync(0xffffffffu, s, o);
    __shared__ float ss[8];
    if ((t & 31) == 0) ss[t >> 5] = s;
    __syncthreads();
    if (t == 0) {
        float r = 0.f;
        #pragma unroll
        for (int i = 0; i < 8; i++) r += ss[i];
        bp[l * DIM + n] = r + bo[l * DIM + n];
    }
}

__global__ __launch_bounds__(256) void ln_half_k(
    const float* __restrict__ h, const float* __restrict__ g,
    const float* __restrict__ b, const float* __restrict__ ada,
    int so, int sho, __half* __restrict__ oh)
{
    const int row = blockIdx.x, t = threadIdx.x;
    float4 v = ((const float4*)(h + (size_t)row * DIM))[t];
    float s = v.x + v.y + v.z + v.w;
    float q = v.x*v.x + v.y*v.y + v.z*v.z + v.w*v.w;
    #pragma unroll
    for (int o = 16; o; o >>= 1) {
        s += __shfl_xor_sync(0xffffffffu, s, o);
        q += __shfl_xor_sync(0xffffffffu, q, o);
    }
    __shared__ float ss[8], qs[8];
    if ((t & 31) == 0) { ss[t >> 5] = s; qs[t >> 5] = q; }
    __syncthreads();
    s = 0.f; q = 0.f;
    #pragma unroll
    for (int i = 0; i < 8; i++) { s += ss[i]; q += qs[i]; }
    const float m = s * (1.f / DIM);
    const float inv = rsqrtf(q * (1.f / DIM) - m * m + 1e-5f);
    const int c = t * 4;
    float o0 = (v.x - m) * inv * g[c+0] + b[c+0];
    float o1 = (v.y - m) * inv * g[c+1] + b[c+1];
    float o2 = (v.z - m) * inv * g[c+2] + b[c+2];
    float o3 = (v.w - m) * inv * g[c+3] + b[c+3];
    if (ada) {
        const float* ar = ada + (size_t)row * (16 * DIM);
        o0 = o0 * (1.f + ar[so+c+0]) + ar[sho+c+0];
        o1 = o1 * (1.f + ar[so+c+1]) + ar[sho+c+1];
        o2 = o2 * (1.f + ar[so+c+2]) + ar[sho+c+2];
        o3 = o3 * (1.f + ar[so+c+3]) + ar[sho+c+3];
    }
    *(uint2*)(oh + (size_t)row * DIM + c) =
        make_uint2(pack2(__float2half_rn(o0), __float2half_rn(o1)),
                   pack2(__float2half_rn(o2), __float2half_rn(o3)));
}

// ---- launch ----
extern "C" void kernel_launch(void* const* d_in, const int* in_sizes, int n_in,
                              void* d_out, int out_size)
{
    const float* x        = (const float*)d_in[0];
    const float* t_emb    = (const float*)d_in[1];
    const float* condition= (const float*)d_in[2];
    const float* in_w     = (const float*)d_in[3];
    const float* in_b     = (const float*)d_in[4];
    const float* ln1_g    = (const float*)d_in[5];
    const float* ln1_b    = (const float*)d_in[6];
    const float* wqkv     = (const float*)d_in[7];
    const float* bqkv     = (const float*)d_in[8];
    const float* wo       = (const float*)d_in[9];
    const float* bo       = (const float*)d_in[10];
    const float* ln2_g    = (const float*)d_in[11];
    const float* ln2_b    = (const float*)d_in[12];
    const float* w1       = (const float*)d_in[13];
    const float* b1       = (const float*)d_in[14];
    const float* w2       = (const float*)d_in[15];
    const float* b2       = (const float*)d_in[16];
    const float* ada_w    = (const float*)d_in[17];
    const float* ada_b    = (const float*)d_in[18];
    const float* out_ln_g = (const float*)d_in[19];
    const float* out_ln_b = (const float*)d_in[20];
    const float* out_w    = (const float*)d_in[21];
    const float* out_b    = (const float*)d_in[22];

    float *h, *ada, *bp, *zero;
    __half *xh,*st,*big,*w,*woh,*wvt,*wp;
    cudaGetSymbolAddress((void**)&h,    g_h);
    cudaGetSymbolAddress((void**)&ada,  g_ada);
    cudaGetSymbolAddress((void**)&bp,   g_bp);
    cudaGetSymbolAddress((void**)&zero, g_zero);
    cudaGetSymbolAddress((void**)&xh,   g_xh);
    cudaGetSymbolAddress((void**)&st,   g_st);
    cudaGetSymbolAddress((void**)&big,  g_big);
    cudaGetSymbolAddress((void**)&w,    g_w);
    cudaGetSymbolAddress((void**)&woh,  g_woh);
    cudaGetSymbolAddress((void**)&wvt,  g_wvt);
    cudaGetSymbolAddress((void**)&wp,   g_wp);

    cudaFuncSetAttribute(gemm_tc<EP_BIAS>,  cudaFuncAttributeMaxDynamicSharedMemorySize, SMEMSZ);
    cudaFuncSetAttribute(gemm_tc<EP_ADD>,   cudaFuncAttributeMaxDynamicSharedMemorySize, SMEMSZ);
    cudaFuncSetAttribute(gemm_tc<EP_RESID>, cudaFuncAttributeMaxDynamicSharedMemorySize, SMEMSZ);
    cudaFuncSetAttribute(gemm_tc<EP_GELUH>, cudaFuncAttributeMaxDynamicSharedMemorySize, SMEMSZ);
    cudaFuncSetAttribute(gemm_tc<EP_HALF>,  cudaFuncAttributeMaxDynamicSharedMemorySize, SMEMSZ);

    const size_t OFF_ADA = D2, OFF_W1 = 5 * D2, OFF_W2 = 21 * D2, OFF_OUT = 37 * D2;

    const int sb = 256;
    auto cvt = [&](const float* src, __half* o, size_t n) {
        cvt_k<0><<<(int)((n / 4 + sb - 1) / sb), sb>>>(src, o, (int)n);
    };

    cvt(x, xh, (size_t)BATCH * DIM);
    cvt_k<1><<<(BATCH * TEMB / 4 + sb - 1) / sb, sb>>>(t_emb, st, BATCH * TEMB);
    cvt(in_w,  w,           D2);
    cvt(ada_w, w + OFF_ADA, 4 * D2);
    cvt(w1,    w + OFF_W1,  16 * D2);
    cvt(w2,    w + OFF_W2,  16 * D2);
    cvt(out_w, w + OFF_OUT, D2);
    cvt(wo,    woh,         4 * D2);
    transpose_wv<<<dim3(32, 32, NL), dim3(32, 8)>>>(wqkv, wvt);
    bprime_k<<<dim3(DIM, NL), 256>>>(wo, bqkv, bo, bp);

    const dim3 blk(NTHR);
    const dim3 gD  (DIM / BN, BATCH / BM);        // (4, 32)
    const dim3 g4D (4 * DIM / BN, BATCH / BM);    // (16, 32)
    const dim3 gAda(16 * DIM / BN, BATCH / BM);   // (64, 32)
    const dim3 gWp (DIM / BN, DIM / BM, NL);      // (4, 8, 4)

    gemm_tc<EP_HALF><<<gWp, blk, SMEMSZ>>>(woh, wvt, zero, nullptr,
                                           nullptr, wp, DIM, DIM, D2, D2, D2);
    gemm_tc<EP_BIAS><<<gAda, blk, SMEMSZ>>>(st, w + OFF_ADA, ada_b, nullptr,
                                            ada, nullptr, 16 * DIM, TEMB, 0, 0, 0);
    gemm_tc<EP_ADD><<<gD, blk, SMEMSZ>>>(xh, w, in_b, condition,
                                         h, nullptr, DIM, DIM, 0, 0, 0);

    for (int l = 0; l < NL; l++) {
        const int ao = l * 4 * DIM;
        ln_half_k<<<BATCH, 256>>>(h, ln1_g + (size_t)l * DIM, ln1_b + (size_t)l * DIM,
                                  ada, ao, ao + DIM, xh);
        gemm_tc<EP_RESID><<<gD, blk, SMEMSZ>>>(xh, wp + (size_t)l * D2,
                                               bp + (size_t)l * DIM, nullptr,
                                               h, nullptr, DIM, DIM, 0, 0, 0);
        ln_half_k<<<BATCH, 256>>>(h, ln2_g + (size_t)l * DIM, ln2_b + (size_t)l * DIM,
                                  ada, ao + 2 * DIM, ao + 3 * DIM, xh);
        gemm_tc<EP_GELUH><<<g4D, blk, SMEMSZ>>>(xh, w + OFF_W1 + (size_t)l * 4 * D2,
                                                b1 + (size_t)l * 4 * DIM, nullptr,
                                                nullptr, big, 4 * DIM, DIM, 0, 0, 0);
        gemm_tc<EP_RESID><<<gD, blk, SMEMSZ>>>(big, w + OFF_W2 + (size_t)l * 4 * D2,
                                               b2 + (size_t)l * DIM, nullptr,
                                               h, nullptr, DIM, 4 * DIM, 0, 0, 0);
    }

    ln_half_k<<<BATCH, 256>>>(h, out_ln_g, out_ln_b, nullptr, 0, 0, xh);
    gemm_tc<EP_BIAS><<<gD, blk, SMEMSZ>>>(xh, w + OFF_OUT, out_b, nullptr,
                                          (float*)d_out, nullptr, DIM, DIM, 0, 0, 0);
}